// round 5
// baseline (speedup 1.0000x reference)
#include <cuda_runtime.h>
#include <cuda_bf16.h>
#include <math.h>
#include <stdint.h>

#define B_    2048
#define S_    128
#define D_    1024
#define DFF_  4096
#define NCAND 32
#define NACT  546

#define K3    (3*D_)          // 3072: sections [hi | lo | hi] x [hi | hi | lo]
#define BM    128
#define BN    128
#define BK    64
#define NCH   (K3/BK)         // 48
#define STAGES 3
#define GT    256             // 8 warps: 2m x 4n, warp tile 64x32

#define STAGE_BYTES 32768     // A 16KB + B 16KB
#define SM_TOTAL (STAGES*STAGE_BYTES)

// ---------------- scratch ----------------
__device__ __nv_bfloat16 g_A3[(size_t)B_   * K3];   // 12 MB
__device__ __nv_bfloat16 g_B3t[(size_t)DFF_ * K3];  // 24 MB, [n][k]

// ---------------- helpers ----------------
__device__ __forceinline__ uint32_t smem_u32(const void* p) {
    uint32_t a;
    asm("{ .reg .u64 t; cvta.to.shared.u64 t, %1; cvt.u32.u64 %0, t; }" : "=r"(a) : "l"(p));
    return a;
}
__device__ __forceinline__ void cp_async16(uint32_t s, const void* g) {
    asm volatile("cp.async.cg.shared.global [%0], [%1], 16;" :: "r"(s), "l"(g));
}
#define CP_COMMIT() asm volatile("cp.async.commit_group;" ::: "memory")
template <int N>
__device__ __forceinline__ void cp_wait() {
    asm volatile("cp.async.wait_group %0;" :: "n"(N) : "memory");
}
__device__ __forceinline__ void ldsm_x4(uint32_t* r, uint32_t addr) {
    asm volatile("ldmatrix.sync.aligned.m8n8.x4.shared.b16 {%0,%1,%2,%3}, [%4];"
                 : "=r"(r[0]), "=r"(r[1]), "=r"(r[2]), "=r"(r[3]) : "r"(addr));
}
__device__ __forceinline__ void mma16816(float* d, const uint32_t* a, uint32_t b0, uint32_t b1) {
    asm volatile("mma.sync.aligned.m16n8k16.row.col.f32.bf16.bf16.f32 "
                 "{%0,%1,%2,%3}, {%4,%5,%6,%7}, {%8,%9}, {%0,%1,%2,%3};"
                 : "+f"(d[0]), "+f"(d[1]), "+f"(d[2]), "+f"(d[3])
                 : "r"(a[0]), "r"(a[1]), "r"(a[2]), "r"(a[3]), "r"(b0), "r"(b1));
}
__device__ __forceinline__ float gelu_exact(float x) {
    return 0.5f * x * (1.0f + erff(x * 0.70710678118654752f));
}
__device__ __forceinline__ uint32_t swz(int r, int c2) {
    return (uint32_t)(r * 128 + ((c2 * 16) ^ ((r & 7) * 16)));
}
__device__ __forceinline__ uint32_t pack_bf16x2(float x, float y) {
    __nv_bfloat162 v;
    v.x = __float2bfloat16(x); v.y = __float2bfloat16(y);
    return *(uint32_t*)&v;
}

// ---------------- kernel 1: fused sentinel + gather + split A ----------------
// grid 2048, block 256. Each block: 1 row, float4 loads (1 iter), 8B stores.
__global__ void convA_kernel(const int* __restrict__ cand,
                             const float* __restrict__ encode,
                             const float* __restrict__ b2,
                             float* __restrict__ out) {
    const int b = blockIdx.x;
    __shared__ int srow;
    if (threadIdx.x < 32) {
        int c = cand[b * NCAND + threadIdx.x];
        unsigned m = __ballot_sync(0xffffffffu, c >= NACT);
        if (threadIdx.x == 0) {
            srow = (S_ - NCAND) + (__ffs(m) - 1);
            out[b] = b2[0];
        }
    }
    __syncthreads();
    const float4* src = (const float4*)(encode + ((size_t)b * S_ + srow) * D_);
    __nv_bfloat16* dst = g_A3 + (size_t)b * K3;
    const int i = threadIdx.x;            // 256 float4 cover D_=1024
    float4 a = src[i];
    float h0f, h1f, h2f, h3f;
    uint32_t hv0, hv1, lv0, lv1;
    {
        __nv_bfloat16 h0 = __float2bfloat16(a.x), h1 = __float2bfloat16(a.y);
        __nv_bfloat16 h2 = __float2bfloat16(a.z), h3 = __float2bfloat16(a.w);
        h0f = __bfloat162float(h0); h1f = __bfloat162float(h1);
        h2f = __bfloat162float(h2); h3f = __bfloat162float(h3);
        __nv_bfloat162 p01; p01.x = h0; p01.y = h1;
        __nv_bfloat162 p23; p23.x = h2; p23.y = h3;
        hv0 = *(uint32_t*)&p01; hv1 = *(uint32_t*)&p23;
    }
    lv0 = pack_bf16x2(a.x - h0f, a.y - h1f);
    lv1 = pack_bf16x2(a.z - h2f, a.w - h3f);
    uint2 hv; hv.x = hv0; hv.y = hv1;
    uint2 lv; lv.x = lv0; lv.y = lv1;
    *(uint2*)(dst + 4 * i)           = hv;
    *(uint2*)(dst + D_ + 4 * i)      = lv;
    *(uint2*)(dst + 2 * D_ + 4 * i)  = hv;
}

// ---------------- kernel 2: transpose + split W1 -> [hi | hi | lo] ----------------
// grid (DFF/64, D/32), block 256: 32k x 64n tile, float4 loads, 16B stores.
__global__ void convB_kernel(const float* __restrict__ W1) {
    __shared__ float tile[32][68];   // 68-float rows: 16B-aligned, conflict-free reads
    const int n0 = blockIdx.x * 64;
    const int k0 = blockIdx.y * 32;
    {
        const int r  = threadIdx.x >> 4;        // 0..15 (two passes)
        const int c4 = (threadIdx.x & 15) * 4;  // float4 col
        #pragma unroll
        for (int rr = r; rr < 32; rr += 16) {
            float4 v = *(const float4*)&W1[(size_t)(k0 + rr) * DFF_ + n0 + c4];
            *(float4*)&tile[rr][c4] = v;
        }
    }
    __syncthreads();
    {
        const int n  = threadIdx.x & 63;          // consecutive lanes -> consecutive n
        const int kq = (threadIdx.x >> 6) * 8;    // 0,8,16,24
        uint32_t hi[4], lo[4];
        #pragma unroll
        for (int i = 0; i < 4; i++) {
            float w0 = tile[kq + 2 * i][n];
            float w1 = tile[kq + 2 * i + 1][n];
            __nv_bfloat16 h0 = __float2bfloat16(w0), h1 = __float2bfloat16(w1);
            __nv_bfloat162 hp; hp.x = h0; hp.y = h1;
            hi[i] = *(uint32_t*)&hp;
            lo[i] = pack_bf16x2(w0 - __bfloat162float(h0), w1 - __bfloat162float(h1));
        }
        __nv_bfloat16* dst = g_B3t + (size_t)(n0 + n) * K3 + k0 + kq;
        *(uint4*)(dst)          = *(uint4*)hi;
        *(uint4*)(dst + D_)     = *(uint4*)hi;
        *(uint4*)(dst + 2 * D_) = *(uint4*)lo;
    }
}

// ---------------- kernel 3: bf16 HMMA GEMM + fused epilogue ----------------
__global__ __launch_bounds__(GT, 2)
void gemm_kernel(const float* __restrict__ b1,
                 const float* __restrict__ W2,
                 float* __restrict__ out) {
    extern __shared__ char smem[];
    const uint32_t sb = smem_u32(smem);
    const int tid  = threadIdx.x;
    const int wid  = tid >> 5;
    const int lane = tid & 31;
    const int wm = wid >> 2;     // 0..1
    const int wn = wid & 3;      // 0..3
    const int bn = blockIdx.x;   // 0..31
    const int bm = blockIdx.y;   // 0..15

    // ---- cp.async mapping: 8 marching pointers + fixed swizzled smem offsets
    const int lr  = tid >> 3;    // row 0..31
    const int lc2 = tid & 7;     // 16B chunk in row
    const char* aPtr[4];
    const char* bPtr[4];
    uint32_t aSw[4], bSw[4];
    {
        const __nv_bfloat16* Ag = g_A3  + (size_t)(bm * BM) * K3 + lc2 * 8;
        const __nv_bfloat16* Bg = g_B3t + (size_t)(bn * BN) * K3 + lc2 * 8;
        #pragma unroll
        for (int i = 0; i < 4; i++) {
            int r = lr + i * 32;
            aPtr[i] = (const char*)(Ag + (size_t)r * K3);
            bPtr[i] = (const char*)(Bg + (size_t)r * K3);
            aSw[i] = swz(r, lc2);
            bSw[i] = swz(r, lc2) + 16384;
        }
    }

    // ---- ldmatrix address constants (swizzle algebra hoist)
    const int l15 = lane & 15;
    const uint32_t xb  = (uint32_t)(l15 & 7) * 16;
    const uint32_t hlx = ((uint32_t)(lane >> 4) * 16) ^ (xb & 16);
    const uint32_t xh  = xb & 0x60;
    uint32_t ksoff[4];
    #pragma unroll
    for (int ks = 0; ks < 4; ks++) ksoff[ks] = ((uint32_t)ks * 32) ^ xh;
    const uint32_t arow0 = (uint32_t)(wm * 64 + l15) * 128 + hlx;
    const uint32_t brow0 = (uint32_t)(wn * 32 + l15) * 128 + hlx + 16384;

    float acc[4][4][4];
    #pragma unroll
    for (int i = 0; i < 4; i++)
        #pragma unroll
        for (int j = 0; j < 4; j++)
            #pragma unroll
            for (int r = 0; r < 4; r++) acc[i][j][r] = 0.f;

    auto load_stage = [&](uint32_t sbase) {
        #pragma unroll
        for (int i = 0; i < 4; i++) {
            cp_async16(sbase + aSw[i], aPtr[i]);
            cp_async16(sbase + bSw[i], bPtr[i]);
            aPtr[i] += BK * 2;
            bPtr[i] += BK * 2;
        }
    };

    load_stage(sb + 0 * STAGE_BYTES); CP_COMMIT();
    load_stage(sb + 1 * STAGE_BYTES); CP_COMMIT();

    uint32_t afr[2][4][4], bfr[2][2][4];

    for (int c = 0; c < NCH; c++) {
        cp_wait<1>();
        __syncthreads();
        if (c + 2 < NCH) { load_stage(sb + ((c + 2) % STAGES) * STAGE_BYTES); CP_COMMIT(); }

        const uint32_t sA = sb + (c % STAGES) * STAGE_BYTES;

        // prefetch ks=0 fragments
        {
            const uint32_t s0 = sA + ksoff[0];
            #pragma unroll
            for (int mt = 0; mt < 4; mt++) ldsm_x4(afr[0][mt], s0 + arow0 + mt * 2048);
            #pragma unroll
            for (int u = 0; u < 2; u++)    ldsm_x4(bfr[0][u],  s0 + brow0 + u * 2048);
        }

        #pragma unroll
        for (int ks = 0; ks < 4; ks++) {
            const int cur = ks & 1;
            if (ks < 3) {   // prefetch ks+1 while MMAs of ks run
                const uint32_t sn = sA + ksoff[ks + 1];
                #pragma unroll
                for (int mt = 0; mt < 4; mt++) ldsm_x4(afr[cur ^ 1][mt], sn + arow0 + mt * 2048);
                #pragma unroll
                for (int u = 0; u < 2; u++)    ldsm_x4(bfr[cur ^ 1][u],  sn + brow0 + u * 2048);
            }
            #pragma unroll
            for (int mt = 0; mt < 4; mt++)
                #pragma unroll
                for (int nt = 0; nt < 4; nt++)
                    mma16816(acc[mt][nt], afr[cur][mt],
                             bfr[cur][nt >> 1][nt & 1], bfr[cur][nt >> 1][(nt & 1) + 2]);
        }
    }

    // ---- Epilogue: bias + exact gelu + dot W2, reduce, atomicAdd ----
    const int qn = lane & 3;
    const int qr = lane >> 2;
    float bia[4][2], w2v[4][2];
    #pragma unroll
    for (int nt = 0; nt < 4; nt++) {
        int n = bn * BN + wn * 32 + nt * 8 + qn * 2;
        bia[nt][0] = __ldg(&b1[n]);     bia[nt][1] = __ldg(&b1[n + 1]);
        w2v[nt][0] = __ldg(&W2[n]);     w2v[nt][1] = __ldg(&W2[n + 1]);
    }
    #pragma unroll
    for (int mt = 0; mt < 4; mt++) {
        float p0 = 0.f, p1 = 0.f;
        #pragma unroll
        for (int nt = 0; nt < 4; nt++) {
            const float* d = acc[mt][nt];
            p0 = fmaf(gelu_exact(d[0] + bia[nt][0]), w2v[nt][0], p0);
            p0 = fmaf(gelu_exact(d[1] + bia[nt][1]), w2v[nt][1], p0);
            p1 = fmaf(gelu_exact(d[2] + bia[nt][0]), w2v[nt][0], p1);
            p1 = fmaf(gelu_exact(d[3] + bia[nt][1]), w2v[nt][1], p1);
        }
        p0 += __shfl_xor_sync(0xffffffffu, p0, 1);
        p0 += __shfl_xor_sync(0xffffffffu, p0, 2);
        p1 += __shfl_xor_sync(0xffffffffu, p1, 1);
        p1 += __shfl_xor_sync(0xffffffffu, p1, 2);
        if (qn == 0) {
            int m = bm * BM + wm * 64 + mt * 16 + qr;
            atomicAdd(&out[m], p0);
            atomicAdd(&out[m + 8], p1);
        }
    }
}

// ---------------- launcher ----------------
extern "C" void kernel_launch(void* const* d_in, const int* in_sizes, int n_in,
                              void* d_out, int out_size) {
    const int*   cand   = (const int*)d_in[0];
    const float* encode = (const float*)d_in[1];
    const float* W1     = (const float*)d_in[2];
    const float* b1     = (const float*)d_in[3];
    const float* W2     = (const float*)d_in[4];
    const float* b2     = (const float*)d_in[5];
    float* out = (float*)d_out;

    static int smem_set = 0;
    if (!smem_set) {
        cudaFuncSetAttribute(gemm_kernel, cudaFuncAttributeMaxDynamicSharedMemorySize, SM_TOTAL);
        smem_set = 1;
    }

    convA_kernel<<<B_, 256>>>(cand, encode, b2, out);
    {
        dim3 g(DFF_ / 64, D_ / 32);
        convB_kernel<<<g, 256>>>(W1);
    }
    {
        dim3 g(DFF_ / BN, B_ / BM);   // (32, 16)
        gemm_kernel<<<g, GT, SM_TOTAL>>>(b1, W2, out);
    }
}

// round 6
// speedup vs baseline: 1.0115x; 1.0115x over previous
#include <cuda_runtime.h>
#include <cuda_bf16.h>
#include <math.h>
#include <stdint.h>

#define B_    2048
#define S_    128
#define D_    1024
#define DFF_  4096
#define NCAND 32
#define NACT  546

#define K3    (3*D_)          // 3072: sections [hi | lo | hi] x [hi | hi | lo]
#define BM    128
#define BN    128
#define BK    64
#define NCH   (K3/BK)         // 48
#define STAGES 3
#define GT    256             // 8 warps: 2m x 4n, warp tile 64x32

#define STAGE_BYTES 32768     // A 16KB + B 16KB
#define SM_TOTAL (STAGES*STAGE_BYTES)

// ---------------- scratch ----------------
__device__ __nv_bfloat16 g_A3[(size_t)B_   * K3];   // 12 MB
__device__ __nv_bfloat16 g_B3t[(size_t)DFF_ * K3];  // 24 MB, [n][k]

// ---------------- helpers ----------------
__device__ __forceinline__ uint32_t smem_u32(const void* p) {
    uint32_t a;
    asm("{ .reg .u64 t; cvta.to.shared.u64 t, %1; cvt.u32.u64 %0, t; }" : "=r"(a) : "l"(p));
    return a;
}
__device__ __forceinline__ void cp_async16(uint32_t s, const void* g) {
    asm volatile("cp.async.cg.shared.global [%0], [%1], 16;" :: "r"(s), "l"(g));
}
#define CP_COMMIT() asm volatile("cp.async.commit_group;" ::: "memory")
template <int N>
__device__ __forceinline__ void cp_wait() {
    asm volatile("cp.async.wait_group %0;" :: "n"(N) : "memory");
}
__device__ __forceinline__ void ldsm_x4(uint32_t* r, uint32_t addr) {
    asm volatile("ldmatrix.sync.aligned.m8n8.x4.shared.b16 {%0,%1,%2,%3}, [%4];"
                 : "=r"(r[0]), "=r"(r[1]), "=r"(r[2]), "=r"(r[3]) : "r"(addr));
}
__device__ __forceinline__ void mma16816(float* d, const uint32_t* a, uint32_t b0, uint32_t b1) {
    asm volatile("mma.sync.aligned.m16n8k16.row.col.f32.bf16.bf16.f32 "
                 "{%0,%1,%2,%3}, {%4,%5,%6,%7}, {%8,%9}, {%0,%1,%2,%3};"
                 : "+f"(d[0]), "+f"(d[1]), "+f"(d[2]), "+f"(d[3])
                 : "r"(a[0]), "r"(a[1]), "r"(a[2]), "r"(a[3]), "r"(b0), "r"(b1));
}
__device__ __forceinline__ float gelu_exact(float x) {
    return 0.5f * x * (1.0f + erff(x * 0.70710678118654752f));
}
__device__ __forceinline__ uint32_t swz(int r, int c2) {
    return (uint32_t)(r * 128 + ((c2 * 16) ^ ((r & 7) * 16)));
}
__device__ __forceinline__ uint32_t pack_bf16x2(float x, float y) {
    __nv_bfloat162 v;
    v.x = __float2bfloat16(x); v.y = __float2bfloat16(y);
    return *(uint32_t*)&v;
}

// ---------------- kernel 1: fused sentinel + gather + split A ----------------
// grid 256, block 256: 8 rows per block, 8 float4 per thread (MLP=8).
__global__ void convA_kernel(const int* __restrict__ cand,
                             const float* __restrict__ encode,
                             const float* __restrict__ b2,
                             float* __restrict__ out) {
    const int b0 = blockIdx.x * 8;
    __shared__ int srow[8];
    const int w = threadIdx.x >> 5, lane = threadIdx.x & 31;
    if (w < 8) {
        int c = cand[(b0 + w) * NCAND + lane];
        unsigned m = __ballot_sync(0xffffffffu, c >= NACT);
        if (lane == 0) {
            srow[w] = (S_ - NCAND) + (__ffs(m) - 1);
            out[b0 + w] = b2[0];
        }
    }
    __syncthreads();
    const int i = threadIdx.x;   // float4 index within a row
    #pragma unroll
    for (int r = 0; r < 8; r++) {
        const int b = b0 + r;
        float4 a = ((const float4*)(encode + ((size_t)b * S_ + srow[r]) * D_))[i];
        __nv_bfloat16 h0 = __float2bfloat16(a.x), h1 = __float2bfloat16(a.y);
        __nv_bfloat16 h2 = __float2bfloat16(a.z), h3 = __float2bfloat16(a.w);
        __nv_bfloat162 p01; p01.x = h0; p01.y = h1;
        __nv_bfloat162 p23; p23.x = h2; p23.y = h3;
        uint2 hv; hv.x = *(uint32_t*)&p01; hv.y = *(uint32_t*)&p23;
        uint2 lv;
        lv.x = pack_bf16x2(a.x - __bfloat162float(h0), a.y - __bfloat162float(h1));
        lv.y = pack_bf16x2(a.z - __bfloat162float(h2), a.w - __bfloat162float(h3));
        __nv_bfloat16* dst = g_A3 + (size_t)b * K3;
        *(uint2*)(dst + 4 * i)          = hv;
        *(uint2*)(dst + D_ + 4 * i)     = lv;
        *(uint2*)(dst + 2 * D_ + 4 * i) = hv;
    }
}

// ---------------- kernel 2: transpose + split W1 -> [hi | hi | lo] ----------------
__global__ void convB_kernel(const float* __restrict__ W1) {
    __shared__ float tile[32][68];
    const int n0 = blockIdx.x * 64;
    const int k0 = blockIdx.y * 32;
    {
        const int r  = threadIdx.x >> 4;
        const int c4 = (threadIdx.x & 15) * 4;
        #pragma unroll
        for (int rr = r; rr < 32; rr += 16) {
            float4 v = *(const float4*)&W1[(size_t)(k0 + rr) * DFF_ + n0 + c4];
            *(float4*)&tile[rr][c4] = v;
        }
    }
    __syncthreads();
    {
        const int n  = threadIdx.x & 63;
        const int kq = (threadIdx.x >> 6) * 8;
        uint32_t hi[4], lo[4];
        #pragma unroll
        for (int i = 0; i < 4; i++) {
            float w0 = tile[kq + 2 * i][n];
            float w1 = tile[kq + 2 * i + 1][n];
            __nv_bfloat16 h0 = __float2bfloat16(w0), h1 = __float2bfloat16(w1);
            __nv_bfloat162 hp; hp.x = h0; hp.y = h1;
            hi[i] = *(uint32_t*)&hp;
            lo[i] = pack_bf16x2(w0 - __bfloat162float(h0), w1 - __bfloat162float(h1));
        }
        __nv_bfloat16* dst = g_B3t + (size_t)(n0 + n) * K3 + k0 + kq;
        *(uint4*)(dst)          = *(uint4*)hi;
        *(uint4*)(dst + D_)     = *(uint4*)hi;
        *(uint4*)(dst + 2 * D_) = *(uint4*)lo;
    }
}

// ---------------- kernel 3: bf16 HMMA GEMM + fused epilogue ----------------
__global__ __launch_bounds__(GT, 2)
void gemm_kernel(const float* __restrict__ b1,
                 const float* __restrict__ W2,
                 float* __restrict__ out) {
    extern __shared__ char smem[];
    const uint32_t sb = smem_u32(smem);
    const int tid  = threadIdx.x;
    const int wid  = tid >> 5;
    const int lane = tid & 31;
    const int wm = wid >> 2;     // 0..1
    const int wn = wid & 3;      // 0..3
    const int bn = blockIdx.x;   // 0..31
    const int bm = blockIdx.y;   // 0..15

    // ---- cp.async mapping
    const int lr  = tid >> 3;
    const int lc2 = tid & 7;
    const char* aPtr[4];
    const char* bPtr[4];
    uint32_t aSw[4], bSw[4];
    {
        const __nv_bfloat16* Ag = g_A3  + (size_t)(bm * BM) * K3 + lc2 * 8;
        const __nv_bfloat16* Bg = g_B3t + (size_t)(bn * BN) * K3 + lc2 * 8;
        #pragma unroll
        for (int i = 0; i < 4; i++) {
            int r = lr + i * 32;
            aPtr[i] = (const char*)(Ag + (size_t)r * K3);
            bPtr[i] = (const char*)(Bg + (size_t)r * K3);
            aSw[i] = swz(r, lc2);
            bSw[i] = swz(r, lc2) + 16384;
        }
    }

    // ---- ldmatrix address constants (swizzle algebra hoist)
    const int l15 = lane & 15;
    const uint32_t xb  = (uint32_t)(l15 & 7) * 16;
    const uint32_t hlx = ((uint32_t)(lane >> 4) * 16) ^ (xb & 16);
    const uint32_t xh  = xb & 0x60;
    uint32_t ksoff[4];
    #pragma unroll
    for (int ks = 0; ks < 4; ks++) ksoff[ks] = ((uint32_t)ks * 32) ^ xh;
    const uint32_t arow0 = (uint32_t)(wm * 64 + l15) * 128 + hlx;
    const uint32_t brow0 = (uint32_t)(wn * 32 + l15) * 128 + hlx + 16384;

    float acc[4][4][4];
    #pragma unroll
    for (int i = 0; i < 4; i++)
        #pragma unroll
        for (int j = 0; j < 4; j++)
            #pragma unroll
            for (int r = 0; r < 4; r++) acc[i][j][r] = 0.f;

    auto load_stage = [&](uint32_t sbase) {
        #pragma unroll
        for (int i = 0; i < 4; i++) {
            cp_async16(sbase + aSw[i], aPtr[i]);
            cp_async16(sbase + bSw[i], bPtr[i]);
            aPtr[i] += BK * 2;
            bPtr[i] += BK * 2;
        }
    };

    load_stage(sb + 0 * STAGE_BYTES); CP_COMMIT();
    load_stage(sb + 1 * STAGE_BYTES); CP_COMMIT();

    uint32_t aF[2][4];        // A frag: current + next (8 regs)
    uint32_t bF[2][2][4];     // B frags double-buffered across ks (16 regs)

    for (int c = 0; c < NCH; c++) {
        cp_wait<1>();
        __syncthreads();
        if (c + 2 < NCH) { load_stage(sb + ((c + 2) % STAGES) * STAGE_BYTES); CP_COMMIT(); }

        const uint32_t sA = sb + (c % STAGES) * STAGE_BYTES;

        // prologue: B frags of ks=0 and A frag of (ks=0, mt=0)
        ldsm_x4(bF[0][0], sA + ksoff[0] + brow0);
        ldsm_x4(bF[0][1], sA + ksoff[0] + brow0 + 2048);
        ldsm_x4(aF[0],    sA + ksoff[0] + arow0);

        #pragma unroll
        for (int ks = 0; ks < 4; ks++) {
            const int kb = ks & 1;
            #pragma unroll
            for (int mt = 0; mt < 4; mt++) {
                const int cur = mt & 1;
                // one ldsm ahead of each 4-MMA group
                if (mt < 3)
                    ldsm_x4(aF[cur ^ 1], sA + ksoff[ks] + arow0 + (mt + 1) * 2048);
                else if (ks < 3)
                    ldsm_x4(aF[cur ^ 1], sA + ksoff[ks + 1] + arow0);
                if (mt == 2 && ks < 3) {
                    ldsm_x4(bF[kb ^ 1][0], sA + ksoff[ks + 1] + brow0);
                    ldsm_x4(bF[kb ^ 1][1], sA + ksoff[ks + 1] + brow0 + 2048);
                }
                #pragma unroll
                for (int nt = 0; nt < 4; nt++)
                    mma16816(acc[mt][nt], aF[cur],
                             bF[kb][nt >> 1][nt & 1], bF[kb][nt >> 1][(nt & 1) + 2]);
            }
        }
    }

    // ---- Epilogue: bias + exact gelu + dot W2, reduce, atomicAdd ----
    const int qn = lane & 3;
    const int qr = lane >> 2;
    float bia[4][2], w2v[4][2];
    #pragma unroll
    for (int nt = 0; nt < 4; nt++) {
        int n = bn * BN + wn * 32 + nt * 8 + qn * 2;
        bia[nt][0] = __ldg(&b1[n]);     bia[nt][1] = __ldg(&b1[n + 1]);
        w2v[nt][0] = __ldg(&W2[n]);     w2v[nt][1] = __ldg(&W2[n + 1]);
    }
    #pragma unroll
    for (int mt = 0; mt < 4; mt++) {
        float p0 = 0.f, p1 = 0.f;
        #pragma unroll
        for (int nt = 0; nt < 4; nt++) {
            const float* d = acc[mt][nt];
            p0 = fmaf(gelu_exact(d[0] + bia[nt][0]), w2v[nt][0], p0);
            p0 = fmaf(gelu_exact(d[1] + bia[nt][1]), w2v[nt][1], p0);
            p1 = fmaf(gelu_exact(d[2] + bia[nt][0]), w2v[nt][0], p1);
            p1 = fmaf(gelu_exact(d[3] + bia[nt][1]), w2v[nt][1], p1);
        }
        p0 += __shfl_xor_sync(0xffffffffu, p0, 1);
        p0 += __shfl_xor_sync(0xffffffffu, p0, 2);
        p1 += __shfl_xor_sync(0xffffffffu, p1, 1);
        p1 += __shfl_xor_sync(0xffffffffu, p1, 2);
        if (qn == 0) {
            int m = bm * BM + wm * 64 + mt * 16 + qr;
            atomicAdd(&out[m], p0);
            atomicAdd(&out[m + 8], p1);
        }
    }
}

// ---------------- launcher ----------------
extern "C" void kernel_launch(void* const* d_in, const int* in_sizes, int n_in,
                              void* d_out, int out_size) {
    const int*   cand   = (const int*)d_in[0];
    const float* encode = (const float*)d_in[1];
    const float* W1     = (const float*)d_in[2];
    const float* b1     = (const float*)d_in[3];
    const float* W2     = (const float*)d_in[4];
    const float* b2     = (const float*)d_in[5];
    float* out = (float*)d_out;

    static int smem_set = 0;
    if (!smem_set) {
        cudaFuncSetAttribute(gemm_kernel, cudaFuncAttributeMaxDynamicSharedMemorySize, SM_TOTAL);
        smem_set = 1;
    }

    convA_kernel<<<B_ / 8, 256>>>(cand, encode, b2, out);
    {
        dim3 g(DFF_ / 64, D_ / 32);
        convB_kernel<<<g, 256>>>(W1);
    }
    {
        dim3 g(DFF_ / BN, B_ / BM);   // (32, 16)
        gemm_kernel<<<g, GT, SM_TOTAL>>>(b1, W2, out);
    }
}

// round 7
// speedup vs baseline: 1.0315x; 1.0198x over previous
#include <cuda_runtime.h>
#include <cuda_bf16.h>
#include <math.h>
#include <stdint.h>

#define B_    2048
#define S_    128
#define D_    1024
#define DFF_  4096
#define NCAND 32
#define NACT  546

#define K3    (3*D_)          // 3072: sections [hi | lo | hi] x [hi | hi | lo]
#define BM    128
#define BN    128
#define BK    64
#define NCH   (K3/BK)         // 48
#define STAGES 3
#define GT    128             // 4 warps: 2m x 2n, warp tile 64x64

#define STAGE_BYTES 32768     // A 16KB + B 16KB
#define SM_TOTAL (STAGES*STAGE_BYTES)

// ---------------- scratch ----------------
__device__ __nv_bfloat16 g_A3[(size_t)B_   * K3];   // 12 MB
__device__ __nv_bfloat16 g_B3t[(size_t)DFF_ * K3];  // 24 MB, [n][k]

// ---------------- helpers ----------------
__device__ __forceinline__ uint32_t smem_u32(const void* p) {
    uint32_t a;
    asm("{ .reg .u64 t; cvta.to.shared.u64 t, %1; cvt.u32.u64 %0, t; }" : "=r"(a) : "l"(p));
    return a;
}
__device__ __forceinline__ void cp_async16(uint32_t s, const void* g) {
    asm volatile("cp.async.cg.shared.global [%0], [%1], 16;" :: "r"(s), "l"(g));
}
#define CP_COMMIT() asm volatile("cp.async.commit_group;" ::: "memory")
template <int N>
__device__ __forceinline__ void cp_wait() {
    asm volatile("cp.async.wait_group %0;" :: "n"(N) : "memory");
}
__device__ __forceinline__ void ldsm_x4(uint32_t* r, uint32_t addr) {
    asm volatile("ldmatrix.sync.aligned.m8n8.x4.shared.b16 {%0,%1,%2,%3}, [%4];"
                 : "=r"(r[0]), "=r"(r[1]), "=r"(r[2]), "=r"(r[3]) : "r"(addr));
}
__device__ __forceinline__ void mma16816(float* d, const uint32_t* a, uint32_t b0, uint32_t b1) {
    asm volatile("mma.sync.aligned.m16n8k16.row.col.f32.bf16.bf16.f32 "
                 "{%0,%1,%2,%3}, {%4,%5,%6,%7}, {%8,%9}, {%0,%1,%2,%3};"
                 : "+f"(d[0]), "+f"(d[1]), "+f"(d[2]), "+f"(d[3])
                 : "r"(a[0]), "r"(a[1]), "r"(a[2]), "r"(a[3]), "r"(b0), "r"(b1));
}
__device__ __forceinline__ float gelu_exact(float x) {
    return 0.5f * x * (1.0f + erff(x * 0.70710678118654752f));
}
__device__ __forceinline__ uint32_t swz(int r, int c2) {
    return (uint32_t)(r * 128 + ((c2 * 16) ^ ((r & 7) * 16)));
}
__device__ __forceinline__ uint32_t pack_bf16x2(float x, float y) {
    __nv_bfloat162 v;
    v.x = __float2bfloat16(x); v.y = __float2bfloat16(y);
    return *(uint32_t*)&v;
}

// ---------------- kernel 1: fused sentinel + gather + split A ----------------
__global__ void convA_kernel(const int* __restrict__ cand,
                             const float* __restrict__ encode,
                             const float* __restrict__ b2,
                             float* __restrict__ out) {
    const int b0 = blockIdx.x * 8;
    __shared__ int srow[8];
    const int w = threadIdx.x >> 5, lane = threadIdx.x & 31;
    if (w < 8) {
        int c = cand[(b0 + w) * NCAND + lane];
        unsigned m = __ballot_sync(0xffffffffu, c >= NACT);
        if (lane == 0) {
            srow[w] = (S_ - NCAND) + (__ffs(m) - 1);
            out[b0 + w] = b2[0];
        }
    }
    __syncthreads();
    const int i = threadIdx.x;
    #pragma unroll
    for (int r = 0; r < 8; r++) {
        const int b = b0 + r;
        float4 a = ((const float4*)(encode + ((size_t)b * S_ + srow[r]) * D_))[i];
        __nv_bfloat16 h0 = __float2bfloat16(a.x), h1 = __float2bfloat16(a.y);
        __nv_bfloat16 h2 = __float2bfloat16(a.z), h3 = __float2bfloat16(a.w);
        __nv_bfloat162 p01; p01.x = h0; p01.y = h1;
        __nv_bfloat162 p23; p23.x = h2; p23.y = h3;
        uint2 hv; hv.x = *(uint32_t*)&p01; hv.y = *(uint32_t*)&p23;
        uint2 lv;
        lv.x = pack_bf16x2(a.x - __bfloat162float(h0), a.y - __bfloat162float(h1));
        lv.y = pack_bf16x2(a.z - __bfloat162float(h2), a.w - __bfloat162float(h3));
        __nv_bfloat16* dst = g_A3 + (size_t)b * K3;
        *(uint2*)(dst + 4 * i)          = hv;
        *(uint2*)(dst + D_ + 4 * i)     = lv;
        *(uint2*)(dst + 2 * D_ + 4 * i) = hv;
    }
}

// ---------------- kernel 2: transpose + split W1 -> [hi | hi | lo] ----------------
__global__ void convB_kernel(const float* __restrict__ W1) {
    __shared__ float tile[32][68];
    const int n0 = blockIdx.x * 64;
    const int k0 = blockIdx.y * 32;
    {
        const int r  = threadIdx.x >> 4;
        const int c4 = (threadIdx.x & 15) * 4;
        #pragma unroll
        for (int rr = r; rr < 32; rr += 16) {
            float4 v = *(const float4*)&W1[(size_t)(k0 + rr) * DFF_ + n0 + c4];
            *(float4*)&tile[rr][c4] = v;
        }
    }
    __syncthreads();
    {
        const int n  = threadIdx.x & 63;
        const int kq = (threadIdx.x >> 6) * 8;
        uint32_t hi[4], lo[4];
        #pragma unroll
        for (int i = 0; i < 4; i++) {
            float w0 = tile[kq + 2 * i][n];
            float w1 = tile[kq + 2 * i + 1][n];
            __nv_bfloat16 h0 = __float2bfloat16(w0), h1 = __float2bfloat16(w1);
            __nv_bfloat162 hp; hp.x = h0; hp.y = h1;
            hi[i] = *(uint32_t*)&hp;
            lo[i] = pack_bf16x2(w0 - __bfloat162float(h0), w1 - __bfloat162float(h1));
        }
        __nv_bfloat16* dst = g_B3t + (size_t)(n0 + n) * K3 + k0 + kq;
        *(uint4*)(dst)          = *(uint4*)hi;
        *(uint4*)(dst + D_)     = *(uint4*)hi;
        *(uint4*)(dst + 2 * D_) = *(uint4*)lo;
    }
}

// ---------------- kernel 3: bf16 HMMA GEMM, warp tile 64x64 ----------------
__global__ __launch_bounds__(GT, 2)
void gemm_kernel(const float* __restrict__ b1,
                 const float* __restrict__ W2,
                 float* __restrict__ out) {
    extern __shared__ char smem[];
    const uint32_t sb = smem_u32(smem);
    const int tid  = threadIdx.x;
    const int wid  = tid >> 5;
    const int lane = tid & 31;
    const int wm = wid >> 1;     // 0..1
    const int wn = wid & 1;      // 0..1
    const int bn = blockIdx.x;   // 0..31
    const int bm = blockIdx.y;   // 0..15

    // ---- cp.async mapping: 128 threads, 8 A-rows + 8 B-rows per thread
    const int lr  = tid >> 3;    // row 0..15 (stride 16)
    const int lc2 = tid & 7;     // 16B chunk in row
    const char* aP;
    const char* bP;
    const uint32_t aSw0 = swz(lr, lc2);            // (lr+16i) keeps (row&7): +i*2048
    const uint32_t bSw0 = aSw0 + 16384;
    {
        aP = (const char*)(g_A3  + (size_t)(bm * BM + lr) * K3 + lc2 * 8);
        bP = (const char*)(g_B3t + (size_t)(bn * BN + lr) * K3 + lc2 * 8);
    }
    const size_t RSTRIDE = (size_t)16 * K3 * 2;    // 16 rows

    // ---- ldmatrix address constants (swizzle algebra hoist)
    const int l15 = lane & 15;
    const uint32_t xb  = (uint32_t)(l15 & 7) * 16;
    const uint32_t hlx = ((uint32_t)(lane >> 4) * 16) ^ (xb & 16);
    const uint32_t xh  = xb & 0x60;
    uint32_t ksoff[4];
    #pragma unroll
    for (int ks = 0; ks < 4; ks++) ksoff[ks] = ((uint32_t)ks * 32) ^ xh;
    const uint32_t arow0 = (uint32_t)(wm * 64 + l15) * 128 + hlx;
    const uint32_t brow0 = (uint32_t)(wn * 64 + l15) * 128 + hlx + 16384;

    float acc[4][8][4];
    #pragma unroll
    for (int i = 0; i < 4; i++)
        #pragma unroll
        for (int j = 0; j < 8; j++)
            #pragma unroll
            for (int r = 0; r < 4; r++) acc[i][j][r] = 0.f;

    auto load_stage = [&](uint32_t sbase) {
        #pragma unroll
        for (int i = 0; i < 8; i++) {
            cp_async16(sbase + aSw0 + i * 2048, aP + i * RSTRIDE);
            cp_async16(sbase + bSw0 + i * 2048, bP + i * RSTRIDE);
        }
        aP += BK * 2;
        bP += BK * 2;
    };

    load_stage(sb + 0 * STAGE_BYTES); CP_COMMIT();
    load_stage(sb + 1 * STAGE_BYTES); CP_COMMIT();

    for (int c = 0; c < NCH; c++) {
        cp_wait<1>();
        __syncthreads();
        if (c + 2 < NCH) { load_stage(sb + ((c + 2) % STAGES) * STAGE_BYTES); CP_COMMIT(); }

        const uint32_t sA = sb + (c % STAGES) * STAGE_BYTES;

        #pragma unroll
        for (int ks = 0; ks < 4; ks++) {
            const uint32_t sks = sA + ksoff[ks];
            uint32_t afr[4][4], bfr[4][4];
            #pragma unroll
            for (int mt = 0; mt < 4; mt++) ldsm_x4(afr[mt], sks + arow0 + mt * 2048);
            #pragma unroll
            for (int u = 0; u < 4; u++)   ldsm_x4(bfr[u],  sks + brow0 + u * 2048);
            #pragma unroll
            for (int mt = 0; mt < 4; mt++)
                #pragma unroll
                for (int nt = 0; nt < 8; nt++)
                    mma16816(acc[mt][nt], afr[mt],
                             bfr[nt >> 1][nt & 1], bfr[nt >> 1][(nt & 1) + 2]);
        }
    }

    // ---- Epilogue: bias + exact gelu + dot W2, reduce, atomicAdd ----
    const int qn = lane & 3;
    const int qr = lane >> 2;
    float bia[8][2], w2v[8][2];
    #pragma unroll
    for (int nt = 0; nt < 8; nt++) {
        int n = bn * BN + wn * 64 + nt * 8 + qn * 2;
        bia[nt][0] = __ldg(&b1[n]);     bia[nt][1] = __ldg(&b1[n + 1]);
        w2v[nt][0] = __ldg(&W2[n]);     w2v[nt][1] = __ldg(&W2[n + 1]);
    }
    #pragma unroll
    for (int mt = 0; mt < 4; mt++) {
        float p0 = 0.f, p1 = 0.f;
        #pragma unroll
        for (int nt = 0; nt < 8; nt++) {
            const float* d = acc[mt][nt];
            p0 = fmaf(gelu_exact(d[0] + bia[nt][0]), w2v[nt][0], p0);
            p0 = fmaf(gelu_exact(d[1] + bia[nt][1]), w2v[nt][1], p0);
            p1 = fmaf(gelu_exact(d[2] + bia[nt][0]), w2v[nt][0], p1);
            p1 = fmaf(gelu_exact(d[3] + bia[nt][1]), w2v[nt][1], p1);
        }
        p0 += __shfl_xor_sync(0xffffffffu, p0, 1);
        p0 += __shfl_xor_sync(0xffffffffu, p0, 2);
        p1 += __shfl_xor_sync(0xffffffffu, p1, 1);
        p1 += __shfl_xor_sync(0xffffffffu, p1, 2);
        if (qn == 0) {
            int m = bm * BM + wm * 64 + mt * 16 + qr;
            atomicAdd(&out[m], p0);
            atomicAdd(&out[m + 8], p1);
        }
    }
}

// ---------------- launcher ----------------
extern "C" void kernel_launch(void* const* d_in, const int* in_sizes, int n_in,
                              void* d_out, int out_size) {
    const int*   cand   = (const int*)d_in[0];
    const float* encode = (const float*)d_in[1];
    const float* W1     = (const float*)d_in[2];
    const float* b1     = (const float*)d_in[3];
    const float* W2     = (const float*)d_in[4];
    const float* b2     = (const float*)d_in[5];
    float* out = (float*)d_out;

    static int smem_set = 0;
    if (!smem_set) {
        cudaFuncSetAttribute(gemm_kernel, cudaFuncAttributeMaxDynamicSharedMemorySize, SM_TOTAL);
        smem_set = 1;
    }

    convA_kernel<<<B_ / 8, 256>>>(cand, encode, b2, out);
    {
        dim3 g(DFF_ / 64, D_ / 32);
        convB_kernel<<<g, 256>>>(W1);
    }
    {
        dim3 g(DFF_ / BN, B_ / BM);   // (32, 16)
        gemm_kernel<<<g, GT, SM_TOTAL>>>(b1, W2, out);
    }
}

// round 8
// speedup vs baseline: 1.4381x; 1.3942x over previous
#include <cuda_runtime.h>
#include <cuda_fp16.h>
#include <math.h>
#include <stdint.h>

#define B_    2048
#define S_    128
#define D_    1024
#define DFF_  4096
#define NCAND 32
#define NACT  546

#define K2    (2*D_)          // 2048: A sections [hi | lo], B sections [hi | hi]
#define BM    128
#define BN    128
#define BK    64
#define NCH   (K2/BK)         // 32
#define STAGES 3
#define GT    256             // 8 warps: 2m x 4n, warp tile 64x32

#define STAGE_BYTES 32768     // A 16KB + B 16KB
#define SM_TOTAL (STAGES*STAGE_BYTES)

// ---------------- scratch ----------------
__device__ __half g_A2[(size_t)B_   * K2];   // 8 MB
__device__ __half g_B2t[(size_t)DFF_ * K2];  // 16 MB, [n][k]

// ---------------- helpers ----------------
__device__ __forceinline__ uint32_t smem_u32(const void* p) {
    uint32_t a;
    asm("{ .reg .u64 t; cvta.to.shared.u64 t, %1; cvt.u32.u64 %0, t; }" : "=r"(a) : "l"(p));
    return a;
}
__device__ __forceinline__ void cp_async16(uint32_t s, const void* g) {
    asm volatile("cp.async.cg.shared.global [%0], [%1], 16;" :: "r"(s), "l"(g));
}
#define CP_COMMIT() asm volatile("cp.async.commit_group;" ::: "memory")
template <int N>
__device__ __forceinline__ void cp_wait() {
    asm volatile("cp.async.wait_group %0;" :: "n"(N) : "memory");
}
__device__ __forceinline__ void ldsm_x4(uint32_t* r, uint32_t addr) {
    asm volatile("ldmatrix.sync.aligned.m8n8.x4.shared.b16 {%0,%1,%2,%3}, [%4];"
                 : "=r"(r[0]), "=r"(r[1]), "=r"(r[2]), "=r"(r[3]) : "r"(addr));
}
__device__ __forceinline__ void mma16816(float* d, const uint32_t* a, uint32_t b0, uint32_t b1) {
    asm volatile("mma.sync.aligned.m16n8k16.row.col.f32.f16.f16.f32 "
                 "{%0,%1,%2,%3}, {%4,%5,%6,%7}, {%8,%9}, {%0,%1,%2,%3};"
                 : "+f"(d[0]), "+f"(d[1]), "+f"(d[2]), "+f"(d[3])
                 : "r"(a[0]), "r"(a[1]), "r"(a[2]), "r"(a[3]), "r"(b0), "r"(b1));
}
__device__ __forceinline__ float gelu_exact(float x) {
    return 0.5f * x * (1.0f + erff(x * 0.70710678118654752f));
}
__device__ __forceinline__ uint32_t swz(int r, int c2) {
    return (uint32_t)(r * 128 + ((c2 * 16) ^ ((r & 7) * 16)));
}
__device__ __forceinline__ uint32_t pack_h2(__half x, __half y) {
    __half2 v; v.x = x; v.y = y;
    return *(uint32_t*)&v;
}

// ---------------- kernel 1: fused sentinel + gather + split A -> [hi | lo] ----------------
// grid 512, block 256: 4 rows per block.
__global__ void convA_kernel(const int* __restrict__ cand,
                             const float* __restrict__ encode,
                             const float* __restrict__ b2,
                             float* __restrict__ out) {
    const int b0 = blockIdx.x * 4;
    __shared__ int srow[4];
    const int w = threadIdx.x >> 5, lane = threadIdx.x & 31;
    if (w < 4) {
        int c = cand[(b0 + w) * NCAND + lane];
        unsigned m = __ballot_sync(0xffffffffu, c >= NACT);
        if (lane == 0) {
            srow[w] = (S_ - NCAND) + (__ffs(m) - 1);
            out[b0 + w] = b2[0];
        }
    }
    __syncthreads();
    const int i = threadIdx.x;   // 256 float4 cover D_=1024
    #pragma unroll
    for (int r = 0; r < 4; r++) {
        const int b = b0 + r;
        float4 a = ((const float4*)(encode + ((size_t)b * S_ + srow[r]) * D_))[i];
        __half h0 = __float2half_rn(a.x), h1 = __float2half_rn(a.y);
        __half h2 = __float2half_rn(a.z), h3 = __float2half_rn(a.w);
        uint2 hv;
        hv.x = pack_h2(h0, h1);
        hv.y = pack_h2(h2, h3);
        uint2 lv;
        lv.x = pack_h2(__float2half_rn(a.x - __half2float(h0)),
                       __float2half_rn(a.y - __half2float(h1)));
        lv.y = pack_h2(__float2half_rn(a.z - __half2float(h2)),
                       __float2half_rn(a.w - __half2float(h3)));
        __half* dst = g_A2 + (size_t)b * K2;
        *(uint2*)(dst + 4 * i)      = hv;
        *(uint2*)(dst + D_ + 4 * i) = lv;
    }
}

// ---------------- kernel 2: transpose W1 -> [hi | hi] ----------------
__global__ void convB_kernel(const float* __restrict__ W1) {
    __shared__ float tile[32][68];
    const int n0 = blockIdx.x * 64;
    const int k0 = blockIdx.y * 32;
    {
        const int r  = threadIdx.x >> 4;
        const int c4 = (threadIdx.x & 15) * 4;
        #pragma unroll
        for (int rr = r; rr < 32; rr += 16) {
            float4 v = *(const float4*)&W1[(size_t)(k0 + rr) * DFF_ + n0 + c4];
            *(float4*)&tile[rr][c4] = v;
        }
    }
    __syncthreads();
    {
        const int n  = threadIdx.x & 63;
        const int kq = (threadIdx.x >> 6) * 8;
        uint32_t hi[4];
        #pragma unroll
        for (int i = 0; i < 4; i++) {
            hi[i] = pack_h2(__float2half_rn(tile[kq + 2 * i][n]),
                            __float2half_rn(tile[kq + 2 * i + 1][n]));
        }
        __half* dst = g_B2t + (size_t)(n0 + n) * K2 + k0 + kq;
        *(uint4*)(dst)      = *(uint4*)hi;
        *(uint4*)(dst + D_) = *(uint4*)hi;
    }
}

// ---------------- kernel 3: fp16 HMMA GEMM + fused epilogue ----------------
__global__ __launch_bounds__(GT, 2)
void gemm_kernel(const float* __restrict__ b1,
                 const float* __restrict__ W2,
                 float* __restrict__ out) {
    extern __shared__ char smem[];
    const uint32_t sb = smem_u32(smem);
    const int tid  = threadIdx.x;
    const int wid  = tid >> 5;
    const int lane = tid & 31;
    const int wm = wid >> 2;     // 0..1
    const int wn = wid & 3;      // 0..3
    const int bn = blockIdx.x;   // 0..31
    const int bm = blockIdx.y;   // 0..15

    // ---- cp.async mapping: 8 marching pointers + fixed swizzled smem offsets
    const int lr  = tid >> 3;    // row 0..31
    const int lc2 = tid & 7;     // 16B chunk in row
    const char* aPtr[4];
    const char* bPtr[4];
    uint32_t aSw[4], bSw[4];
    {
        const __half* Ag = g_A2  + (size_t)(bm * BM) * K2 + lc2 * 8;
        const __half* Bg = g_B2t + (size_t)(bn * BN) * K2 + lc2 * 8;
        #pragma unroll
        for (int i = 0; i < 4; i++) {
            int r = lr + i * 32;
            aPtr[i] = (const char*)(Ag + (size_t)r * K2);
            bPtr[i] = (const char*)(Bg + (size_t)r * K2);
            aSw[i] = swz(r, lc2);
            bSw[i] = swz(r, lc2) + 16384;
        }
    }

    // ---- ldmatrix address constants (swizzle algebra hoist)
    const int l15 = lane & 15;
    const uint32_t xb  = (uint32_t)(l15 & 7) * 16;
    const uint32_t hlx = ((uint32_t)(lane >> 4) * 16) ^ (xb & 16);
    const uint32_t xh  = xb & 0x60;
    uint32_t ksoff[4];
    #pragma unroll
    for (int ks = 0; ks < 4; ks++) ksoff[ks] = ((uint32_t)ks * 32) ^ xh;
    const uint32_t arow0 = (uint32_t)(wm * 64 + l15) * 128 + hlx;
    const uint32_t brow0 = (uint32_t)(wn * 32 + l15) * 128 + hlx + 16384;

    float acc[4][4][4];
    #pragma unroll
    for (int i = 0; i < 4; i++)
        #pragma unroll
        for (int j = 0; j < 4; j++)
            #pragma unroll
            for (int r = 0; r < 4; r++) acc[i][j][r] = 0.f;

    auto load_stage = [&](uint32_t sbase) {
        #pragma unroll
        for (int i = 0; i < 4; i++) {
            cp_async16(sbase + aSw[i], aPtr[i]);
            cp_async16(sbase + bSw[i], bPtr[i]);
            aPtr[i] += BK * 2;
            bPtr[i] += BK * 2;
        }
    };

    load_stage(sb + 0 * STAGE_BYTES); CP_COMMIT();
    load_stage(sb + 1 * STAGE_BYTES); CP_COMMIT();

    for (int c = 0; c < NCH; c++) {
        cp_wait<1>();
        __syncthreads();
        if (c + 2 < NCH) { load_stage(sb + ((c + 2) % STAGES) * STAGE_BYTES); CP_COMMIT(); }

        const uint32_t sA = sb + (c % STAGES) * STAGE_BYTES;

        #pragma unroll
        for (int ks = 0; ks < 4; ks++) {
            const uint32_t sks = sA + ksoff[ks];
            uint32_t afr[4][4], bfr[2][4];
            #pragma unroll
            for (int mt = 0; mt < 4; mt++) ldsm_x4(afr[mt], sks + arow0 + mt * 2048);
            #pragma unroll
            for (int u = 0; u < 2; u++)   ldsm_x4(bfr[u],  sks + brow0 + u * 2048);
            #pragma unroll
            for (int mt = 0; mt < 4; mt++)
                #pragma unroll
                for (int nt = 0; nt < 4; nt++)
                    mma16816(acc[mt][nt], afr[mt],
                             bfr[nt >> 1][nt & 1], bfr[nt >> 1][(nt & 1) + 2]);
        }
    }

    // ---- Epilogue: bias + exact gelu + dot W2, reduce, atomicAdd ----
    const int qn = lane & 3;
    const int qr = lane >> 2;
    float bia[4][2], w2v[4][2];
    #pragma unroll
    for (int nt = 0; nt < 4; nt++) {
        int n = bn * BN + wn * 32 + nt * 8 + qn * 2;
        bia[nt][0] = __ldg(&b1[n]);     bia[nt][1] = __ldg(&b1[n + 1]);
        w2v[nt][0] = __ldg(&W2[n]);     w2v[nt][1] = __ldg(&W2[n + 1]);
    }
    #pragma unroll
    for (int mt = 0; mt < 4; mt++) {
        float p0 = 0.f, p1 = 0.f;
        #pragma unroll
        for (int nt = 0; nt < 4; nt++) {
            const float* d = acc[mt][nt];
            p0 = fmaf(gelu_exact(d[0] + bia[nt][0]), w2v[nt][0], p0);
            p0 = fmaf(gelu_exact(d[1] + bia[nt][1]), w2v[nt][1], p0);
            p1 = fmaf(gelu_exact(d[2] + bia[nt][0]), w2v[nt][0], p1);
            p1 = fmaf(gelu_exact(d[3] + bia[nt][1]), w2v[nt][1], p1);
        }
        p0 += __shfl_xor_sync(0xffffffffu, p0, 1);
        p0 += __shfl_xor_sync(0xffffffffu, p0, 2);
        p1 += __shfl_xor_sync(0xffffffffu, p1, 1);
        p1 += __shfl_xor_sync(0xffffffffu, p1, 2);
        if (qn == 0) {
            int m = bm * BM + wm * 64 + mt * 16 + qr;
            atomicAdd(&out[m], p0);
            atomicAdd(&out[m + 8], p1);
        }
    }
}

// ---------------- launcher ----------------
extern "C" void kernel_launch(void* const* d_in, const int* in_sizes, int n_in,
                              void* d_out, int out_size) {
    const int*   cand   = (const int*)d_in[0];
    const float* encode = (const float*)d_in[1];
    const float* W1     = (const float*)d_in[2];
    const float* b1     = (const float*)d_in[3];
    const float* W2     = (const float*)d_in[4];
    const float* b2     = (const float*)d_in[5];
    float* out = (float*)d_out;

    static int smem_set = 0;
    if (!smem_set) {
        cudaFuncSetAttribute(gemm_kernel, cudaFuncAttributeMaxDynamicSharedMemorySize, SM_TOTAL);
        smem_set = 1;
    }

    convA_kernel<<<B_ / 4, 256>>>(cand, encode, b2, out);
    {
        dim3 g(DFF_ / 64, D_ / 32);
        convB_kernel<<<g, 256>>>(W1);
    }
    {
        dim3 g(DFF_ / BN, B_ / BM);   // (32, 16)
        gemm_kernel<<<g, GT, SM_TOTAL>>>(b1, W2, out);
    }
}

// round 9
// speedup vs baseline: 2.4763x; 1.7219x over previous
#include <cuda_runtime.h>
#include <cuda_fp16.h>
#include <math.h>
#include <stdint.h>

#define B_    2048
#define S_    128
#define D_    1024
#define DFF_  4096
#define NCAND 32
#define NACT  546

#define K1    D_              // 1024: pure fp16, no split sections
#define BM    128
#define BN    128
#define BK    64
#define NCH   (K1/BK)         // 16
#define STAGES 3
#define GT    256             // 8 warps: 2m x 4n, warp tile 64x32

#define STAGE_BYTES 32768     // A 16KB + B 16KB
#define SM_TOTAL (STAGES*STAGE_BYTES)

// ---------------- scratch ----------------
__device__ __half g_A2[(size_t)B_   * K1];   // 4 MB
__device__ __half g_B2t[(size_t)DFF_ * K1];  // 8 MB, [n][k]

// ---------------- helpers ----------------
__device__ __forceinline__ uint32_t smem_u32(const void* p) {
    uint32_t a;
    asm("{ .reg .u64 t; cvta.to.shared.u64 t, %1; cvt.u32.u64 %0, t; }" : "=r"(a) : "l"(p));
    return a;
}
__device__ __forceinline__ void cp_async16(uint32_t s, const void* g) {
    asm volatile("cp.async.cg.shared.global [%0], [%1], 16;" :: "r"(s), "l"(g));
}
#define CP_COMMIT() asm volatile("cp.async.commit_group;" ::: "memory")
template <int N>
__device__ __forceinline__ void cp_wait() {
    asm volatile("cp.async.wait_group %0;" :: "n"(N) : "memory");
}
__device__ __forceinline__ void ldsm_x4(uint32_t* r, uint32_t addr) {
    asm volatile("ldmatrix.sync.aligned.m8n8.x4.shared.b16 {%0,%1,%2,%3}, [%4];"
                 : "=r"(r[0]), "=r"(r[1]), "=r"(r[2]), "=r"(r[3]) : "r"(addr));
}
__device__ __forceinline__ void mma16816(float* d, const uint32_t* a, uint32_t b0, uint32_t b1) {
    asm volatile("mma.sync.aligned.m16n8k16.row.col.f32.f16.f16.f32 "
                 "{%0,%1,%2,%3}, {%4,%5,%6,%7}, {%8,%9}, {%0,%1,%2,%3};"
                 : "+f"(d[0]), "+f"(d[1]), "+f"(d[2]), "+f"(d[3])
                 : "r"(a[0]), "r"(a[1]), "r"(a[2]), "r"(a[3]), "r"(b0), "r"(b1));
}
__device__ __forceinline__ float gelu_exact(float x) {
    return 0.5f * x * (1.0f + erff(x * 0.70710678118654752f));
}
__device__ __forceinline__ uint32_t swz(int r, int c2) {
    return (uint32_t)(r * 128 + ((c2 * 16) ^ ((r & 7) * 16)));
}
__device__ __forceinline__ uint32_t pack_h2(__half x, __half y) {
    __half2 v; v.x = x; v.y = y;
    return *(uint32_t*)&v;
}

// ---------------- kernel 1: fused sentinel + gather + fp16 convert A ----------------
// grid 512, block 256: 4 rows per block.
__global__ void convA_kernel(const int* __restrict__ cand,
                             const float* __restrict__ encode,
                             const float* __restrict__ b2,
                             float* __restrict__ out) {
    const int b0 = blockIdx.x * 4;
    __shared__ int srow[4];
    const int w = threadIdx.x >> 5, lane = threadIdx.x & 31;
    if (w < 4) {
        int c = cand[(b0 + w) * NCAND + lane];
        unsigned m = __ballot_sync(0xffffffffu, c >= NACT);
        if (lane == 0) {
            srow[w] = (S_ - NCAND) + (__ffs(m) - 1);
            out[b0 + w] = b2[0];
        }
    }
    __syncthreads();
    const int i = threadIdx.x;   // 256 float4 cover D_=1024
    #pragma unroll
    for (int r = 0; r < 4; r++) {
        const int b = b0 + r;
        float4 a = ((const float4*)(encode + ((size_t)b * S_ + srow[r]) * D_))[i];
        uint2 hv;
        hv.x = pack_h2(__float2half_rn(a.x), __float2half_rn(a.y));
        hv.y = pack_h2(__float2half_rn(a.z), __float2half_rn(a.w));
        *(uint2*)(g_A2 + (size_t)b * K1 + 4 * i) = hv;
    }
}

// ---------------- kernel 2: transpose W1 -> fp16 [n][k] ----------------
__global__ void convB_kernel(const float* __restrict__ W1) {
    __shared__ float tile[32][68];
    const int n0 = blockIdx.x * 64;
    const int k0 = blockIdx.y * 32;
    {
        const int r  = threadIdx.x >> 4;
        const int c4 = (threadIdx.x & 15) * 4;
        #pragma unroll
        for (int rr = r; rr < 32; rr += 16) {
            float4 v = *(const float4*)&W1[(size_t)(k0 + rr) * DFF_ + n0 + c4];
            *(float4*)&tile[rr][c4] = v;
        }
    }
    __syncthreads();
    {
        const int n  = threadIdx.x & 63;
        const int kq = (threadIdx.x >> 6) * 8;
        uint32_t hi[4];
        #pragma unroll
        for (int i = 0; i < 4; i++) {
            hi[i] = pack_h2(__float2half_rn(tile[kq + 2 * i][n]),
                            __float2half_rn(tile[kq + 2 * i + 1][n]));
        }
        *(uint4*)(g_B2t + (size_t)(n0 + n) * K1 + k0 + kq) = *(uint4*)hi;
    }
}

// ---------------- kernel 3: fp16 HMMA GEMM + fused epilogue ----------------
__global__ __launch_bounds__(GT, 2)
void gemm_kernel(const float* __restrict__ b1,
                 const float* __restrict__ W2,
                 float* __restrict__ out) {
    extern __shared__ char smem[];
    const uint32_t sb = smem_u32(smem);
    const int tid  = threadIdx.x;
    const int wid  = tid >> 5;
    const int lane = tid & 31;
    const int wm = wid >> 2;     // 0..1
    const int wn = wid & 3;      // 0..3
    const int bn = blockIdx.x;   // 0..31
    const int bm = blockIdx.y;   // 0..15

    // ---- cp.async mapping: 8 marching pointers + fixed swizzled smem offsets
    const int lr  = tid >> 3;    // row 0..31
    const int lc2 = tid & 7;     // 16B chunk in row
    const char* aPtr[4];
    const char* bPtr[4];
    uint32_t aSw[4], bSw[4];
    {
        const __half* Ag = g_A2  + (size_t)(bm * BM) * K1 + lc2 * 8;
        const __half* Bg = g_B2t + (size_t)(bn * BN) * K1 + lc2 * 8;
        #pragma unroll
        for (int i = 0; i < 4; i++) {
            int r = lr + i * 32;
            aPtr[i] = (const char*)(Ag + (size_t)r * K1);
            bPtr[i] = (const char*)(Bg + (size_t)r * K1);
            aSw[i] = swz(r, lc2);
            bSw[i] = swz(r, lc2) + 16384;
        }
    }

    // ---- ldmatrix address constants (swizzle algebra hoist)
    const int l15 = lane & 15;
    const uint32_t xb  = (uint32_t)(l15 & 7) * 16;
    const uint32_t hlx = ((uint32_t)(lane >> 4) * 16) ^ (xb & 16);
    const uint32_t xh  = xb & 0x60;
    uint32_t ksoff[4];
    #pragma unroll
    for (int ks = 0; ks < 4; ks++) ksoff[ks] = ((uint32_t)ks * 32) ^ xh;
    const uint32_t arow0 = (uint32_t)(wm * 64 + l15) * 128 + hlx;
    const uint32_t brow0 = (uint32_t)(wn * 32 + l15) * 128 + hlx + 16384;

    float acc[4][4][4];
    #pragma unroll
    for (int i = 0; i < 4; i++)
        #pragma unroll
        for (int j = 0; j < 4; j++)
            #pragma unroll
            for (int r = 0; r < 4; r++) acc[i][j][r] = 0.f;

    auto load_stage = [&](uint32_t sbase) {
        #pragma unroll
        for (int i = 0; i < 4; i++) {
            cp_async16(sbase + aSw[i], aPtr[i]);
            cp_async16(sbase + bSw[i], bPtr[i]);
            aPtr[i] += BK * 2;
            bPtr[i] += BK * 2;
        }
    };

    load_stage(sb + 0 * STAGE_BYTES); CP_COMMIT();
    load_stage(sb + 1 * STAGE_BYTES); CP_COMMIT();

    for (int c = 0; c < NCH; c++) {
        cp_wait<1>();
        __syncthreads();
        if (c + 2 < NCH) { load_stage(sb + ((c + 2) % STAGES) * STAGE_BYTES); CP_COMMIT(); }

        const uint32_t sA = sb + (c % STAGES) * STAGE_BYTES;

        #pragma unroll
        for (int ks = 0; ks < 4; ks++) {
            const uint32_t sks = sA + ksoff[ks];
            uint32_t afr[4][4], bfr[2][4];
            #pragma unroll
            for (int mt = 0; mt < 4; mt++) ldsm_x4(afr[mt], sks + arow0 + mt * 2048);
            #pragma unroll
            for (int u = 0; u < 2; u++)   ldsm_x4(bfr[u],  sks + brow0 + u * 2048);
            #pragma unroll
            for (int mt = 0; mt < 4; mt++)
                #pragma unroll
                for (int nt = 0; nt < 4; nt++)
                    mma16816(acc[mt][nt], afr[mt],
                             bfr[nt >> 1][nt & 1], bfr[nt >> 1][(nt & 1) + 2]);
        }
    }

    // ---- Epilogue: bias + exact gelu + dot W2, reduce, atomicAdd ----
    const int qn = lane & 3;
    const int qr = lane >> 2;
    float bia[4][2], w2v[4][2];
    #pragma unroll
    for (int nt = 0; nt < 4; nt++) {
        int n = bn * BN + wn * 32 + nt * 8 + qn * 2;
        bia[nt][0] = __ldg(&b1[n]);     bia[nt][1] = __ldg(&b1[n + 1]);
        w2v[nt][0] = __ldg(&W2[n]);     w2v[nt][1] = __ldg(&W2[n + 1]);
    }
    #pragma unroll
    for (int mt = 0; mt < 4; mt++) {
        float p0 = 0.f, p1 = 0.f;
        #pragma unroll
        for (int nt = 0; nt < 4; nt++) {
            const float* d = acc[mt][nt];
            p0 = fmaf(gelu_exact(d[0] + bia[nt][0]), w2v[nt][0], p0);
            p0 = fmaf(gelu_exact(d[1] + bia[nt][1]), w2v[nt][1], p0);
            p1 = fmaf(gelu_exact(d[2] + bia[nt][0]), w2v[nt][0], p1);
            p1 = fmaf(gelu_exact(d[3] + bia[nt][1]), w2v[nt][1], p1);
        }
        p0 += __shfl_xor_sync(0xffffffffu, p0, 1);
        p0 += __shfl_xor_sync(0xffffffffu, p0, 2);
        p1 += __shfl_xor_sync(0xffffffffu, p1, 1);
        p1 += __shfl_xor_sync(0xffffffffu, p1, 2);
        if (qn == 0) {
            int m = bm * BM + wm * 64 + mt * 16 + qr;
            atomicAdd(&out[m], p0);
            atomicAdd(&out[m + 8], p1);
        }
    }
}

// ---------------- launcher ----------------
extern "C" void kernel_launch(void* const* d_in, const int* in_sizes, int n_in,
                              void* d_out, int out_size) {
    const int*   cand   = (const int*)d_in[0];
    const float* encode = (const float*)d_in[1];
    const float* W1     = (const float*)d_in[2];
    const float* b1     = (const float*)d_in[3];
    const float* W2     = (const float*)d_in[4];
    const float* b2     = (const float*)d_in[5];
    float* out = (float*)d_out;

    static int smem_set = 0;
    if (!smem_set) {
        cudaFuncSetAttribute(gemm_kernel, cudaFuncAttributeMaxDynamicSharedMemorySize, SM_TOTAL);
        smem_set = 1;
    }

    convA_kernel<<<B_ / 4, 256>>>(cand, encode, b2, out);
    {
        dim3 g(DFF_ / 64, D_ / 32);
        convB_kernel<<<g, 256>>>(W1);
    }
    {
        dim3 g(DFF_ / BN, B_ / BM);   // (32, 16)
        gemm_kernel<<<g, GT, SM_TOTAL>>>(b1, W2, out);
    }
}

// round 11
// speedup vs baseline: 2.5138x; 1.0152x over previous
#include <cuda_runtime.h>
#include <cuda_fp16.h>
#include <math.h>
#include <stdint.h>

#define B_    2048
#define S_    128
#define D_    1024
#define DFF_  4096
#define NCAND 32
#define NACT  546

#define K1    D_              // 1024: pure fp16
#define BM    128
#define BN    128
#define BK    64
#define NCH   (K1/BK)         // 16
#define STAGES 3
#define GT    256             // 8 warps: 2m x 4n, warp tile 64x32

#define STAGE_BYTES 32768     // A 16KB + B 16KB
#define SM_TOTAL (STAGES*STAGE_BYTES)

#define NBLK_A 512            // conv blocks doing A (4 rows each)
#define NBLK_B 2048           // conv blocks doing B: (DFF/64)*(D/32) = 64*32 tiles

// ---------------- scratch ----------------
__device__ __half g_A2[(size_t)B_   * K1];   // 4 MB
__device__ __half g_B2t[(size_t)DFF_ * K1];  // 8 MB, [n][k]

// ---------------- helpers ----------------
__device__ __forceinline__ uint32_t smem_u32(const void* p) {
    uint32_t a;
    asm("{ .reg .u64 t; cvta.to.shared.u64 t, %1; cvt.u32.u64 %0, t; }" : "=r"(a) : "l"(p));
    return a;
}
__device__ __forceinline__ void cp_async16(uint32_t s, const void* g) {
    asm volatile("cp.async.cg.shared.global [%0], [%1], 16;" :: "r"(s), "l"(g));
}
#define CP_COMMIT() asm volatile("cp.async.commit_group;" ::: "memory")
template <int N>
__device__ __forceinline__ void cp_wait() {
    asm volatile("cp.async.wait_group %0;" :: "n"(N) : "memory");
}
__device__ __forceinline__ void ldsm_x4(uint32_t* r, uint32_t addr) {
    asm volatile("ldmatrix.sync.aligned.m8n8.x4.shared.b16 {%0,%1,%2,%3}, [%4];"
                 : "=r"(r[0]), "=r"(r[1]), "=r"(r[2]), "=r"(r[3]) : "r"(addr));
}
__device__ __forceinline__ void mma16816(float* d, const uint32_t* a, uint32_t b0, uint32_t b1) {
    asm volatile("mma.sync.aligned.m16n8k16.row.col.f32.f16.f16.f32 "
                 "{%0,%1,%2,%3}, {%4,%5,%6,%7}, {%8,%9}, {%0,%1,%2,%3};"
                 : "+f"(d[0]), "+f"(d[1]), "+f"(d[2]), "+f"(d[3])
                 : "r"(a[0]), "r"(a[1]), "r"(a[2]), "r"(a[3]), "r"(b0), "r"(b1));
}
__device__ __forceinline__ float gelu_exact(float x) {
    return 0.5f * x * (1.0f + erff(x * 0.70710678118654752f));
}
__device__ __forceinline__ uint32_t swz(int r, int c2) {
    return (uint32_t)(r * 128 + ((c2 * 16) ^ ((r & 7) * 16)));
}
__device__ __forceinline__ uint32_t pack_h2(__half x, __half y) {
    __half2 v; v.x = x; v.y = y;
    return *(uint32_t*)&v;
}

// ---------------- kernel 1: fused conv (A-gather+convert || B-transpose+convert) ----------------
__global__ void conv_kernel(const int* __restrict__ cand,
                            const float* __restrict__ encode,
                            const float* __restrict__ W1,
                            const float* __restrict__ b2,
                            float* __restrict__ out) {
    if (blockIdx.x < NBLK_A) {
        // ---- A path: 4 batch rows per block
        const int b0 = blockIdx.x * 4;
        __shared__ int srow[4];
        const int w = threadIdx.x >> 5, lane = threadIdx.x & 31;
        if (w < 4) {
            int c = cand[(b0 + w) * NCAND + lane];
            unsigned m = __ballot_sync(0xffffffffu, c >= NACT);
            if (lane == 0) {
                srow[w] = (S_ - NCAND) + (__ffs(m) - 1);
                out[b0 + w] = b2[0];
            }
        }
        __syncthreads();
        const int i = threadIdx.x;   // 256 float4 cover D_=1024
        #pragma unroll
        for (int r = 0; r < 4; r++) {
            const int b = b0 + r;
            float4 a = ((const float4*)(encode + ((size_t)b * S_ + srow[r]) * D_))[i];
            uint2 hv;
            hv.x = pack_h2(__float2half_rn(a.x), __float2half_rn(a.y));
            hv.y = pack_h2(__float2half_rn(a.z), __float2half_rn(a.w));
            *(uint2*)(g_A2 + (size_t)b * K1 + 4 * i) = hv;
        }
    } else {
        // ---- B path: transpose W1 -> fp16 [n][k], 64n x 32k tile per block
        __shared__ float tile[32][68];
        const int bb = blockIdx.x - NBLK_A;       // 0..2047
        const int n0 = (bb & 63) * 64;            // 64 n-tiles
        const int k0 = (bb >> 6) * 32;            // 32 k-tiles
        {
            const int r  = threadIdx.x >> 4;
            const int c4 = (threadIdx.x & 15) * 4;
            #pragma unroll
            for (int rr = r; rr < 32; rr += 16) {
                float4 v = *(const float4*)&W1[(size_t)(k0 + rr) * DFF_ + n0 + c4];
                *(float4*)&tile[rr][c4] = v;
            }
        }
        __syncthreads();
        {
            const int n  = threadIdx.x & 63;
            const int kq = (threadIdx.x >> 6) * 8;
            uint32_t hi[4];
            #pragma unroll
            for (int i = 0; i < 4; i++) {
                hi[i] = pack_h2(__float2half_rn(tile[kq + 2 * i][n]),
                                __float2half_rn(tile[kq + 2 * i + 1][n]));
            }
            *(uint4*)(g_B2t + (size_t)(n0 + n) * K1 + k0 + kq) = *(uint4*)hi;
        }
    }
}

// ---------------- kernel 2: fp16 HMMA GEMM + fused epilogue ----------------
__global__ __launch_bounds__(GT, 2)
void gemm_kernel(const float* __restrict__ b1,
                 const float* __restrict__ W2,
                 float* __restrict__ out) {
    extern __shared__ char smem[];
    const uint32_t sb = smem_u32(smem);
    const int tid  = threadIdx.x;
    const int wid  = tid >> 5;
    const int lane = tid & 31;
    const int wm = wid >> 2;     // 0..1
    const int wn = wid & 3;      // 0..3
    const int bn = blockIdx.x;   // 0..31
    const int bm = blockIdx.y;   // 0..15

    // ---- cp.async mapping: 8 marching pointers + fixed swizzled smem offsets
    const int lr  = tid >> 3;    // row 0..31
    const int lc2 = tid & 7;     // 16B chunk in row
    const char* aPtr[4];
    const char* bPtr[4];
    uint32_t aSw[4], bSw[4];
    {
        const __half* Ag = g_A2  + (size_t)(bm * BM) * K1 + lc2 * 8;
        const __half* Bg = g_B2t + (size_t)(bn * BN) * K1 + lc2 * 8;
        #pragma unroll
        for (int i = 0; i < 4; i++) {
            int r = lr + i * 32;
            aPtr[i] = (const char*)(Ag + (size_t)r * K1);
            bPtr[i] = (const char*)(Bg + (size_t)r * K1);
            aSw[i] = swz(r, lc2);
            bSw[i] = swz(r, lc2) + 16384;
        }
    }

    // ---- ldmatrix address constants (swizzle algebra hoist)
    const int l15 = lane & 15;
    const uint32_t xb  = (uint32_t)(l15 & 7) * 16;
    const uint32_t hlx = ((uint32_t)(lane >> 4) * 16) ^ (xb & 16);
    const uint32_t xh  = xb & 0x60;
    uint32_t ksoff[4];
    #pragma unroll
    for (int ks = 0; ks < 4; ks++) ksoff[ks] = ((uint32_t)ks * 32) ^ xh;
    const uint32_t arow0 = (uint32_t)(wm * 64 + l15) * 128 + hlx;
    const uint32_t brow0 = (uint32_t)(wn * 32 + l15) * 128 + hlx + 16384;

    float acc[4][4][4];
    #pragma unroll
    for (int i = 0; i < 4; i++)
        #pragma unroll
        for (int j = 0; j < 4; j++)
            #pragma unroll
            for (int r = 0; r < 4; r++) acc[i][j][r] = 0.f;

    auto load_stage = [&](uint32_t sbase) {
        #pragma unroll
        for (int i = 0; i < 4; i++) {
            cp_async16(sbase + aSw[i], aPtr[i]);
            cp_async16(sbase + bSw[i], bPtr[i]);
            aPtr[i] += BK * 2;
            bPtr[i] += BK * 2;
        }
    };

    load_stage(sb + 0 * STAGE_BYTES); CP_COMMIT();
    load_stage(sb + 1 * STAGE_BYTES); CP_COMMIT();

    for (int c = 0; c < NCH; c++) {
        cp_wait<1>();
        __syncthreads();
        if (c + 2 < NCH) { load_stage(sb + ((c + 2) % STAGES) * STAGE_BYTES); CP_COMMIT(); }

        const uint32_t sA = sb + (c % STAGES) * STAGE_BYTES;

        #pragma unroll
        for (int ks = 0; ks < 4; ks++) {
            const uint32_t sks = sA + ksoff[ks];
            uint32_t afr[4][4], bfr[2][4];
            #pragma unroll
            for (int mt = 0; mt < 4; mt++) ldsm_x4(afr[mt], sks + arow0 + mt * 2048);
            #pragma unroll
            for (int u = 0; u < 2; u++)   ldsm_x4(bfr[u],  sks + brow0 + u * 2048);
            #pragma unroll
            for (int mt = 0; mt < 4; mt++)
                #pragma unroll
                for (int nt = 0; nt < 4; nt++)
                    mma16816(acc[mt][nt], afr[mt],
                             bfr[nt >> 1][nt & 1], bfr[nt >> 1][(nt & 1) + 2]);
        }
    }

    // ---- Epilogue: bias + exact gelu + dot W2, reduce, atomicAdd ----
    const int qn = lane & 3;
    const int qr = lane >> 2;
    float bia[4][2], w2v[4][2];
    #pragma unroll
    for (int nt = 0; nt < 4; nt++) {
        int n = bn * BN + wn * 32 + nt * 8 + qn * 2;
        bia[nt][0] = __ldg(&b1[n]);     bia[nt][1] = __ldg(&b1[n + 1]);
        w2v[nt][0] = __ldg(&W2[n]);     w2v[nt][1] = __ldg(&W2[n + 1]);
    }
    #pragma unroll
    for (int mt = 0; mt < 4; mt++) {
        float p0 = 0.f, p1 = 0.f;
        #pragma unroll
        for (int nt = 0; nt < 4; nt++) {
            const float* d = acc[mt][nt];
            p0 = fmaf(gelu_exact(d[0] + bia[nt][0]), w2v[nt][0], p0);
            p0 = fmaf(gelu_exact(d[1] + bia[nt][1]), w2v[nt][1], p0);
            p1 = fmaf(gelu_exact(d[2] + bia[nt][0]), w2v[nt][0], p1);
            p1 = fmaf(gelu_exact(d[3] + bia[nt][1]), w2v[nt][1], p1);
        }
        p0 += __shfl_xor_sync(0xffffffffu, p0, 1);
        p0 += __shfl_xor_sync(0xffffffffu, p0, 2);
        p1 += __shfl_xor_sync(0xffffffffu, p1, 1);
        p1 += __shfl_xor_sync(0xffffffffu, p1, 2);
        if (qn == 0) {
            int m = bm * BM + wm * 64 + mt * 16 + qr;
            atomicAdd(&out[m], p0);
            atomicAdd(&out[m + 8], p1);
        }
    }
}

// ---------------- launcher ----------------
extern "C" void kernel_launch(void* const* d_in, const int* in_sizes, int n_in,
                              void* d_out, int out_size) {
    const int*   cand   = (const int*)d_in[0];
    const float* encode = (const float*)d_in[1];
    const float* W1     = (const float*)d_in[2];
    const float* b1     = (const float*)d_in[3];
    const float* W2     = (const float*)d_in[4];
    const float* b2     = (const float*)d_in[5];
    float* out = (float*)d_out;

    static int smem_set = 0;
    if (!smem_set) {
        cudaFuncSetAttribute(gemm_kernel, cudaFuncAttributeMaxDynamicSharedMemorySize, SM_TOTAL);
        smem_set = 1;
    }

    conv_kernel<<<NBLK_A + NBLK_B, 256>>>(cand, encode, W1, b2, out);
    {
        dim3 g(DFF_ / BN, B_ / BM);   // (32, 16)
        gemm_kernel<<<g, GT, SM_TOTAL>>>(b1, W2, out);
    }
}

// round 12
// speedup vs baseline: 2.6547x; 1.0561x over previous
#include <cuda_runtime.h>
#include <cuda_fp16.h>
#include <math.h>
#include <stdint.h>

#define B_    2048
#define S_    128
#define D_    1024
#define DFF_  4096
#define NCAND 32
#define NACT  546

#define K1    D_              // 1024: pure fp16
#define BM    128
#define BN    128
#define BK    64
#define NCH   (K1/BK)         // 16
#define STAGES 3
#define GT    256             // 8 warps: 2m x 4n, warp tile 64x32

#define STAGE_BYTES 32768     // A 16KB + B 16KB
#define SM_TOTAL (STAGES*STAGE_BYTES)

#define NBLK_A 512            // conv blocks doing A (4 rows each)
#define NBLK_B 2048           // conv blocks doing B: (DFF/64)*(D/32)

// ---------------- scratch ----------------
__device__ __half g_A2[(size_t)B_   * K1];   // 4 MB
__device__ __half g_B2t[(size_t)DFF_ * K1];  // 8 MB, [n][k]

// ---------------- helpers ----------------
__device__ __forceinline__ uint32_t smem_u32(const void* p) {
    uint32_t a;
    asm("{ .reg .u64 t; cvta.to.shared.u64 t, %1; cvt.u32.u64 %0, t; }" : "=r"(a) : "l"(p));
    return a;
}
__device__ __forceinline__ void cp_async16(uint32_t s, const void* g) {
    asm volatile("cp.async.cg.shared.global [%0], [%1], 16;" :: "r"(s), "l"(g));
}
#define CP_COMMIT() asm volatile("cp.async.commit_group;" ::: "memory")
template <int N>
__device__ __forceinline__ void cp_wait() {
    asm volatile("cp.async.wait_group %0;" :: "n"(N) : "memory");
}
__device__ __forceinline__ void ldsm_x4(uint32_t* r, uint32_t addr) {
    asm volatile("ldmatrix.sync.aligned.m8n8.x4.shared.b16 {%0,%1,%2,%3}, [%4];"
                 : "=r"(r[0]), "=r"(r[1]), "=r"(r[2]), "=r"(r[3]) : "r"(addr));
}
__device__ __forceinline__ void mma16816(float* d, const uint32_t* a, uint32_t b0, uint32_t b1) {
    asm volatile("mma.sync.aligned.m16n8k16.row.col.f32.f16.f16.f32 "
                 "{%0,%1,%2,%3}, {%4,%5,%6,%7}, {%8,%9}, {%0,%1,%2,%3};"
                 : "+f"(d[0]), "+f"(d[1]), "+f"(d[2]), "+f"(d[3])
                 : "r"(a[0]), "r"(a[1]), "r"(a[2]), "r"(a[3]), "r"(b0), "r"(b1));
}
__device__ __forceinline__ float gelu_exact(float x) {
    return 0.5f * x * (1.0f + erff(x * 0.70710678118654752f));
}
__device__ __forceinline__ uint32_t swz(int r, int c2) {
    return (uint32_t)(r * 128 + ((c2 * 16) ^ ((r & 7) * 16)));
}
__device__ __forceinline__ uint32_t pack_h2(__half x, __half y) {
    __half2 v; v.x = x; v.y = y;
    return *(uint32_t*)&v;
}

// ---------------- kernel 1: fused conv (A-gather+convert || B-transpose+convert) ----------------
__global__ void conv_kernel(const int* __restrict__ cand,
                            const float* __restrict__ encode,
                            const float* __restrict__ W1,
                            const float* __restrict__ b2,
                            float* __restrict__ out) {
    if (blockIdx.x < NBLK_A) {
        const int b0 = blockIdx.x * 4;
        __shared__ int srow[4];
        const int w = threadIdx.x >> 5, lane = threadIdx.x & 31;
        if (w < 4) {
            int c = cand[(b0 + w) * NCAND + lane];
            unsigned m = __ballot_sync(0xffffffffu, c >= NACT);
            if (lane == 0) {
                srow[w] = (S_ - NCAND) + (__ffs(m) - 1);
                out[b0 + w] = b2[0];
            }
        }
        __syncthreads();
        const int i = threadIdx.x;
        #pragma unroll
        for (int r = 0; r < 4; r++) {
            const int b = b0 + r;
            float4 a = ((const float4*)(encode + ((size_t)b * S_ + srow[r]) * D_))[i];
            uint2 hv;
            hv.x = pack_h2(__float2half_rn(a.x), __float2half_rn(a.y));
            hv.y = pack_h2(__float2half_rn(a.z), __float2half_rn(a.w));
            *(uint2*)(g_A2 + (size_t)b * K1 + 4 * i) = hv;
        }
    } else {
        __shared__ float tile[32][68];
        const int bb = blockIdx.x - NBLK_A;       // 0..2047
        const int n0 = (bb & 63) * 64;
        const int k0 = (bb >> 6) * 32;
        {
            const int r  = threadIdx.x >> 4;
            const int c4 = (threadIdx.x & 15) * 4;
            #pragma unroll
            for (int rr = r; rr < 32; rr += 16) {
                float4 v = *(const float4*)&W1[(size_t)(k0 + rr) * DFF_ + n0 + c4];
                *(float4*)&tile[rr][c4] = v;
            }
        }
        __syncthreads();
        {
            const int n  = threadIdx.x & 63;
            const int kq = (threadIdx.x >> 6) * 8;
            uint32_t hi[4];
            #pragma unroll
            for (int i = 0; i < 4; i++) {
                hi[i] = pack_h2(__float2half_rn(tile[kq + 2 * i][n]),
                                __float2half_rn(tile[kq + 2 * i + 1][n]));
            }
            *(uint4*)(g_B2t + (size_t)(n0 + n) * K1 + k0 + kq) = *(uint4*)hi;
        }
    }
}

// ---------------- kernel 2: fp16 HMMA GEMM, fully unrolled chunk loop ----------------
__global__ __launch_bounds__(GT, 2)
void gemm_kernel(const float* __restrict__ b1,
                 const float* __restrict__ W2,
                 float* __restrict__ out) {
    extern __shared__ char smem[];
    const uint32_t sb = smem_u32(smem);
    const int tid  = threadIdx.x;
    const int wid  = tid >> 5;
    const int lane = tid & 31;
    const int wm = wid >> 2;     // 0..1
    const int wn = wid & 3;      // 0..3
    const int bn = blockIdx.x;   // 0..31
    const int bm = blockIdx.y;   // 0..15

    // ---- cp.async mapping: FIXED base pointers; chunk offsets are immediates
    const int lr  = tid >> 3;    // row 0..31
    const int lc2 = tid & 7;     // 16B chunk in row
    const char* aPtr[4];
    const char* bPtr[4];
    uint32_t aSw[4], bSw[4];
    {
        const __half* Ag = g_A2  + (size_t)(bm * BM) * K1 + lc2 * 8;
        const __half* Bg = g_B2t + (size_t)(bn * BN) * K1 + lc2 * 8;
        #pragma unroll
        for (int i = 0; i < 4; i++) {
            int r = lr + i * 32;
            aPtr[i] = (const char*)(Ag + (size_t)r * K1);
            bPtr[i] = (const char*)(Bg + (size_t)r * K1);
            aSw[i] = swz(r, lc2);
            bSw[i] = swz(r, lc2) + 16384;
        }
    }

    // ---- ldmatrix address constants (swizzle algebra hoist)
    const int l15 = lane & 15;
    const uint32_t xb  = (uint32_t)(l15 & 7) * 16;
    const uint32_t hlx = ((uint32_t)(lane >> 4) * 16) ^ (xb & 16);
    const uint32_t xh  = xb & 0x60;
    // base ldsm addresses (ks and stage offsets folded as immediates below)
    const uint32_t aBase = sb + (uint32_t)(wm * 64 + l15) * 128 + hlx;
    const uint32_t bBase = sb + (uint32_t)(wn * 32 + l15) * 128 + hlx + 16384;
    const uint32_t xh0 = 0 ^ xh, xh1 = 32 ^ xh, xh2 = 64 ^ xh, xh3 = 96 ^ xh;

    float acc[4][4][4];
    #pragma unroll
    for (int i = 0; i < 4; i++)
        #pragma unroll
        for (int j = 0; j < 4; j++)
            #pragma unroll
            for (int r = 0; r < 4; r++) acc[i][j][r] = 0.f;

    // load stage for chunk c into buffer buf — all offsets compile-time when c,buf are
    #define LOAD_STAGE(buf, c)                                                  \
        do {                                                                    \
            _Pragma("unroll")                                                   \
            for (int i = 0; i < 4; i++) {                                       \
                cp_async16(sb + (buf) * STAGE_BYTES + aSw[i], aPtr[i] + (c) * 128); \
                cp_async16(sb + (buf) * STAGE_BYTES + bSw[i], bPtr[i] + (c) * 128); \
            }                                                                   \
            CP_COMMIT();                                                        \
        } while (0)

    LOAD_STAGE(0, 0);
    LOAD_STAGE(1, 1);

    #pragma unroll
    for (int c = 0; c < NCH; c++) {
        cp_wait<1>();
        __syncthreads();
        if (c + 2 < NCH) LOAD_STAGE((c + 2) % STAGES, c + 2);

        const uint32_t stg = (uint32_t)((c % STAGES) * STAGE_BYTES);
        const uint32_t ksofs[4] = {stg + xh0, stg + xh1, stg + xh2, stg + xh3};

        #pragma unroll
        for (int ks = 0; ks < 4; ks++) {
            uint32_t afr[4][4], bfr[2][4];
            #pragma unroll
            for (int mt = 0; mt < 4; mt++) ldsm_x4(afr[mt], aBase + ksofs[ks] + mt * 2048);
            #pragma unroll
            for (int u = 0; u < 2; u++)   ldsm_x4(bfr[u],  bBase + ksofs[ks] + u * 2048);
            #pragma unroll
            for (int mt = 0; mt < 4; mt++)
                #pragma unroll
                for (int nt = 0; nt < 4; nt++)
                    mma16816(acc[mt][nt], afr[mt],
                             bfr[nt >> 1][nt & 1], bfr[nt >> 1][(nt & 1) + 2]);
        }
    }

    // ---- Epilogue: bias + exact gelu + dot W2, reduce, atomicAdd ----
    const int qn = lane & 3;
    const int qr = lane >> 2;
    float bia[4][2], w2v[4][2];
    #pragma unroll
    for (int nt = 0; nt < 4; nt++) {
        int n = bn * BN + wn * 32 + nt * 8 + qn * 2;
        bia[nt][0] = __ldg(&b1[n]);     bia[nt][1] = __ldg(&b1[n + 1]);
        w2v[nt][0] = __ldg(&W2[n]);     w2v[nt][1] = __ldg(&W2[n + 1]);
    }
    #pragma unroll
    for (int mt = 0; mt < 4; mt++) {
        float p0 = 0.f, p1 = 0.f;
        #pragma unroll
        for (int nt = 0; nt < 4; nt++) {
            const float* d = acc[mt][nt];
            p0 = fmaf(gelu_exact(d[0] + bia[nt][0]), w2v[nt][0], p0);
            p0 = fmaf(gelu_exact(d[1] + bia[nt][1]), w2v[nt][1], p0);
            p1 = fmaf(gelu_exact(d[2] + bia[nt][0]), w2v[nt][0], p1);
            p1 = fmaf(gelu_exact(d[3] + bia[nt][1]), w2v[nt][1], p1);
        }
        p0 += __shfl_xor_sync(0xffffffffu, p0, 1);
        p0 += __shfl_xor_sync(0xffffffffu, p0, 2);
        p1 += __shfl_xor_sync(0xffffffffu, p1, 1);
        p1 += __shfl_xor_sync(0xffffffffu, p1, 2);
        if (qn == 0) {
            int m = bm * BM + wm * 64 + mt * 16 + qr;
            atomicAdd(&out[m], p0);
            atomicAdd(&out[m + 8], p1);
        }
    }
}

// ---------------- launcher ----------------
extern "C" void kernel_launch(void* const* d_in, const int* in_sizes, int n_in,
                              void* d_out, int out_size) {
    const int*   cand   = (const int*)d_in[0];
    const float* encode = (const float*)d_in[1];
    const float* W1     = (const float*)d_in[2];
    const float* b1     = (const float*)d_in[3];
    const float* W2     = (const float*)d_in[4];
    const float* b2     = (const float*)d_in[5];
    float* out = (float*)d_out;

    static int smem_set = 0;
    if (!smem_set) {
        cudaFuncSetAttribute(gemm_kernel, cudaFuncAttributeMaxDynamicSharedMemorySize, SM_TOTAL);
        smem_set = 1;
    }

    conv_kernel<<<NBLK_A + NBLK_B, 256>>>(cand, encode, W1, b2, out);
    {
        dim3 g(DFF_ / BN, B_ / BM);   // (32, 16)
        gemm_kernel<<<g, GT, SM_TOTAL>>>(b1, W2, out);
    }
}

// round 13
// speedup vs baseline: 2.6673x; 1.0047x over previous
#include <cuda_runtime.h>
#include <cuda_fp16.h>
#include <math.h>
#include <stdint.h>

#define B_    2048
#define S_    128
#define D_    1024
#define DFF_  4096
#define NCAND 32
#define NACT  546

#define K1    D_              // 1024: pure fp16
#define BM    128
#define BN    128
#define BK    64
#define NCH   (K1/BK)         // 16
#define STAGES 3
#define GT    256             // 8 warps: 2m x 4n, warp tile 64x32

#define STAGE_BYTES 32768     // A 16KB + B 16KB
#define SM_TOTAL (STAGES*STAGE_BYTES)

#define NBLK_B 2048           // conv blocks doing B first (bandwidth-bound bulk)
#define NBLK_A 512            // conv blocks doing A (4 rows each)

// ---------------- scratch ----------------
__device__ __half g_A2[(size_t)B_   * K1];   // 4 MB
__device__ __half g_B2t[(size_t)DFF_ * K1];  // 8 MB, [n][k]

// ---------------- helpers ----------------
__device__ __forceinline__ uint32_t smem_u32(const void* p) {
    uint32_t a;
    asm("{ .reg .u64 t; cvta.to.shared.u64 t, %1; cvt.u32.u64 %0, t; }" : "=r"(a) : "l"(p));
    return a;
}
__device__ __forceinline__ void cp_async16(uint32_t s, const void* g) {
    asm volatile("cp.async.cg.shared.global [%0], [%1], 16;" :: "r"(s), "l"(g));
}
#define CP_COMMIT() asm volatile("cp.async.commit_group;" ::: "memory")
template <int N>
__device__ __forceinline__ void cp_wait() {
    asm volatile("cp.async.wait_group %0;" :: "n"(N) : "memory");
}
__device__ __forceinline__ void ldsm_x4(uint32_t* r, uint32_t addr) {
    asm volatile("ldmatrix.sync.aligned.m8n8.x4.shared.b16 {%0,%1,%2,%3}, [%4];"
                 : "=r"(r[0]), "=r"(r[1]), "=r"(r[2]), "=r"(r[3]) : "r"(addr));
}
__device__ __forceinline__ void mma16816(float* d, const uint32_t* a, uint32_t b0, uint32_t b1) {
    asm volatile("mma.sync.aligned.m16n8k16.row.col.f32.f16.f16.f32 "
                 "{%0,%1,%2,%3}, {%4,%5,%6,%7}, {%8,%9}, {%0,%1,%2,%3};"
                 : "+f"(d[0]), "+f"(d[1]), "+f"(d[2]), "+f"(d[3])
                 : "r"(a[0]), "r"(a[1]), "r"(a[2]), "r"(a[3]), "r"(b0), "r"(b1));
}
__device__ __forceinline__ float gelu_exact(float x) {
    return 0.5f * x * (1.0f + erff(x * 0.70710678118654752f));
}
__device__ __forceinline__ uint32_t swz(int r, int c2) {
    return (uint32_t)(r * 128 + ((c2 * 16) ^ ((r & 7) * 16)));
}
__device__ __forceinline__ uint32_t pack_h2(__half x, __half y) {
    __half2 v; v.x = x; v.y = y;
    return *(uint32_t*)&v;
}

// ---------------- kernel 1: fused conv (B-transpose+convert first, then A path) ----------------
__global__ void conv_kernel(const int* __restrict__ cand,
                            const float* __restrict__ encode,
                            const float* __restrict__ W1,
                            const float* __restrict__ b2,
                            float* __restrict__ out) {
    if (blockIdx.x < NBLK_B) {
        // ---- B path: transpose W1 -> fp16 [n][k], 64n x 32k tile per block
        __shared__ float tile[32][68];
        const int bb = blockIdx.x;                // 0..2047
        const int n0 = (bb & 63) * 64;
        const int k0 = (bb >> 6) * 32;
        {
            const int r  = threadIdx.x >> 4;
            const int c4 = (threadIdx.x & 15) * 4;
            #pragma unroll
            for (int rr = r; rr < 32; rr += 16) {
                float4 v = *(const float4*)&W1[(size_t)(k0 + rr) * DFF_ + n0 + c4];
                *(float4*)&tile[rr][c4] = v;
            }
        }
        __syncthreads();
        {
            const int n  = threadIdx.x & 63;
            const int kq = (threadIdx.x >> 6) * 8;
            uint32_t hi[4];
            #pragma unroll
            for (int i = 0; i < 4; i++) {
                hi[i] = pack_h2(__float2half_rn(tile[kq + 2 * i][n]),
                                __float2half_rn(tile[kq + 2 * i + 1][n]));
            }
            *(uint4*)(g_B2t + (size_t)(n0 + n) * K1 + k0 + kq) = *(uint4*)hi;
        }
    } else {
        // ---- A path: 4 batch rows per block
        const int b0 = (blockIdx.x - NBLK_B) * 4;
        __shared__ int srow[4];
        const int w = threadIdx.x >> 5, lane = threadIdx.x & 31;
        if (w < 4) {
            int c = cand[(b0 + w) * NCAND + lane];
            unsigned m = __ballot_sync(0xffffffffu, c >= NACT);
            if (lane == 0) {
                srow[w] = (S_ - NCAND) + (__ffs(m) - 1);
                out[b0 + w] = b2[0];
            }
        }
        __syncthreads();
        const int i = threadIdx.x;
        #pragma unroll
        for (int r = 0; r < 4; r++) {
            const int b = b0 + r;
            float4 a = ((const float4*)(encode + ((size_t)b * S_ + srow[r]) * D_))[i];
            uint2 hv;
            hv.x = pack_h2(__float2half_rn(a.x), __float2half_rn(a.y));
            hv.y = pack_h2(__float2half_rn(a.z), __float2half_rn(a.w));
            *(uint2*)(g_A2 + (size_t)b * K1 + 4 * i) = hv;
        }
    }
    cudaTriggerProgrammaticLaunchCompletion();
}

// ---------------- kernel 2: fp16 HMMA GEMM, fully unrolled, PDL-gated ----------------
__global__ __launch_bounds__(GT, 2)
void gemm_kernel(const float* __restrict__ b1,
                 const float* __restrict__ W2,
                 float* __restrict__ out) {
    extern __shared__ char smem[];
    const uint32_t sb = smem_u32(smem);
    const int tid  = threadIdx.x;
    const int wid  = tid >> 5;
    const int lane = tid & 31;
    const int wm = wid >> 2;     // 0..1
    const int wn = wid & 3;      // 0..3
    const int bn = blockIdx.x;   // 0..31
    const int bm = blockIdx.y;   // 0..15

    // ---- prologue (overlaps conv via PDL): address setup only
    const int lr  = tid >> 3;
    const int lc2 = tid & 7;
    const char* aPtr[4];
    const char* bPtr[4];
    uint32_t aSw[4], bSw[4];
    {
        const __half* Ag = g_A2  + (size_t)(bm * BM) * K1 + lc2 * 8;
        const __half* Bg = g_B2t + (size_t)(bn * BN) * K1 + lc2 * 8;
        #pragma unroll
        for (int i = 0; i < 4; i++) {
            int r = lr + i * 32;
            aPtr[i] = (const char*)(Ag + (size_t)r * K1);
            bPtr[i] = (const char*)(Bg + (size_t)r * K1);
            aSw[i] = swz(r, lc2);
            bSw[i] = swz(r, lc2) + 16384;
        }
    }

    const int l15 = lane & 15;
    const uint32_t xb  = (uint32_t)(l15 & 7) * 16;
    const uint32_t hlx = ((uint32_t)(lane >> 4) * 16) ^ (xb & 16);
    const uint32_t xh  = xb & 0x60;
    const uint32_t aBase = sb + (uint32_t)(wm * 64 + l15) * 128 + hlx;
    const uint32_t bBase = sb + (uint32_t)(wn * 32 + l15) * 128 + hlx + 16384;
    const uint32_t xh0 = 0 ^ xh, xh1 = 32 ^ xh, xh2 = 64 ^ xh, xh3 = 96 ^ xh;

    float acc[4][4][4];
    #pragma unroll
    for (int i = 0; i < 4; i++)
        #pragma unroll
        for (int j = 0; j < 4; j++)
            #pragma unroll
            for (int r = 0; r < 4; r++) acc[i][j][r] = 0.f;

    // wait for conv's writes to g_A2/g_B2t before first cp.async
    cudaGridDependencySynchronize();

    #define LOAD_STAGE(buf, c)                                                  \
        do {                                                                    \
            _Pragma("unroll")                                                   \
            for (int i = 0; i < 4; i++) {                                       \
                cp_async16(sb + (buf) * STAGE_BYTES + aSw[i], aPtr[i] + (c) * 128); \
                cp_async16(sb + (buf) * STAGE_BYTES + bSw[i], bPtr[i] + (c) * 128); \
            }                                                                   \
            CP_COMMIT();                                                        \
        } while (0)

    LOAD_STAGE(0, 0);
    LOAD_STAGE(1, 1);

    #pragma unroll
    for (int c = 0; c < NCH; c++) {
        cp_wait<1>();
        __syncthreads();
        if (c + 2 < NCH) LOAD_STAGE((c + 2) % STAGES, c + 2);

        const uint32_t stg = (uint32_t)((c % STAGES) * STAGE_BYTES);
        const uint32_t ksofs[4] = {stg + xh0, stg + xh1, stg + xh2, stg + xh3};

        #pragma unroll
        for (int ks = 0; ks < 4; ks++) {
            uint32_t afr[4][4], bfr[2][4];
            #pragma unroll
            for (int mt = 0; mt < 4; mt++) ldsm_x4(afr[mt], aBase + ksofs[ks] + mt * 2048);
            #pragma unroll
            for (int u = 0; u < 2; u++)   ldsm_x4(bfr[u],  bBase + ksofs[ks] + u * 2048);
            #pragma unroll
            for (int mt = 0; mt < 4; mt++)
                #pragma unroll
                for (int nt = 0; nt < 4; nt++)
                    mma16816(acc[mt][nt], afr[mt],
                             bfr[nt >> 1][nt & 1], bfr[nt >> 1][(nt & 1) + 2]);
        }
    }

    // ---- Epilogue: bias + exact gelu + dot W2, reduce, atomicAdd ----
    const int qn = lane & 3;
    const int qr = lane >> 2;
    float bia[4][2], w2v[4][2];
    #pragma unroll
    for (int nt = 0; nt < 4; nt++) {
        int n = bn * BN + wn * 32 + nt * 8 + qn * 2;
        bia[nt][0] = __ldg(&b1[n]);     bia[nt][1] = __ldg(&b1[n + 1]);
        w2v[nt][0] = __ldg(&W2[n]);     w2v[nt][1] = __ldg(&W2[n + 1]);
    }
    #pragma unroll
    for (int mt = 0; mt < 4; mt++) {
        float p0 = 0.f, p1 = 0.f;
        #pragma unroll
        for (int nt = 0; nt < 4; nt++) {
            const float* d = acc[mt][nt];
            p0 = fmaf(gelu_exact(d[0] + bia[nt][0]), w2v[nt][0], p0);
            p0 = fmaf(gelu_exact(d[1] + bia[nt][1]), w2v[nt][1], p0);
            p1 = fmaf(gelu_exact(d[2] + bia[nt][0]), w2v[nt][0], p1);
            p1 = fmaf(gelu_exact(d[3] + bia[nt][1]), w2v[nt][1], p1);
        }
        p0 += __shfl_xor_sync(0xffffffffu, p0, 1);
        p0 += __shfl_xor_sync(0xffffffffu, p0, 2);
        p1 += __shfl_xor_sync(0xffffffffu, p1, 1);
        p1 += __shfl_xor_sync(0xffffffffu, p1, 2);
        if (qn == 0) {
            int m = bm * BM + wm * 64 + mt * 16 + qr;
            atomicAdd(&out[m], p0);
            atomicAdd(&out[m + 8], p1);
        }
    }
}

// ---------------- launcher ----------------
extern "C" void kernel_launch(void* const* d_in, const int* in_sizes, int n_in,
                              void* d_out, int out_size) {
    const int*   cand   = (const int*)d_in[0];
    const float* encode = (const float*)d_in[1];
    const float* W1     = (const float*)d_in[2];
    const float* b1     = (const float*)d_in[3];
    const float* W2     = (const float*)d_in[4];
    const float* b2     = (const float*)d_in[5];
    float* out = (float*)d_out;

    static int smem_set = 0;
    if (!smem_set) {
        cudaFuncSetAttribute(gemm_kernel, cudaFuncAttributeMaxDynamicSharedMemorySize, SM_TOTAL);
        smem_set = 1;
    }

    conv_kernel<<<NBLK_B + NBLK_A, 256>>>(cand, encode, W1, b2, out);

    // gemm launched with Programmatic Dependent Launch: starts while conv drains
    cudaLaunchConfig_t cfg = {};
    cfg.gridDim  = dim3(DFF_ / BN, B_ / BM, 1);   // (32, 16)
    cfg.blockDim = dim3(GT, 1, 1);
    cfg.dynamicSmemBytes = SM_TOTAL;
    cfg.stream = 0;
    cudaLaunchAttribute attrs[1];
    attrs[0].id = cudaLaunchAttributeProgrammaticStreamSerialization;
    attrs[0].val.programmaticStreamSerializationAllowed = 1;
    cfg.attrs = attrs;
    cfg.numAttrs = 1;
    cudaLaunchKernelEx(&cfg, gemm_kernel, b1, W2, out);
}

// round 14
// speedup vs baseline: 2.9995x; 1.1245x over previous
#include <cuda_runtime.h>
#include <cuda_fp16.h>
#include <math.h>
#include <stdint.h>

#define B_    2048
#define S_    128
#define D_    1024
#define DFF_  4096
#define NCAND 32
#define NACT  546

#define K1    D_              // 1024: pure fp16
#define BM    128
#define BN    64
#define BK    64
#define NCH   (K1/BK)         // 16
#define STAGES 3
#define GT    256             // 8 warps: 4m x 2n, warp tile 32x32

#define STAGE_BYTES 24576     // A 16KB + B 8KB
#define SM_TOTAL (STAGES*STAGE_BYTES)   // 72KB -> 3 CTAs/SM

#define NBLK_B 2048
#define NBLK_A 512

// ---------------- scratch ----------------
__device__ __half g_A2[(size_t)B_   * K1];   // 4 MB
__device__ __half g_B2t[(size_t)DFF_ * K1];  // 8 MB, [n][k]

// ---------------- helpers ----------------
__device__ __forceinline__ uint32_t smem_u32(const void* p) {
    uint32_t a;
    asm("{ .reg .u64 t; cvta.to.shared.u64 t, %1; cvt.u32.u64 %0, t; }" : "=r"(a) : "l"(p));
    return a;
}
__device__ __forceinline__ void cp_async16(uint32_t s, const void* g) {
    asm volatile("cp.async.cg.shared.global [%0], [%1], 16;" :: "r"(s), "l"(g));
}
#define CP_COMMIT() asm volatile("cp.async.commit_group;" ::: "memory")
template <int N>
__device__ __forceinline__ void cp_wait() {
    asm volatile("cp.async.wait_group %0;" :: "n"(N) : "memory");
}
__device__ __forceinline__ void ldsm_x4(uint32_t* r, uint32_t addr) {
    asm volatile("ldmatrix.sync.aligned.m8n8.x4.shared.b16 {%0,%1,%2,%3}, [%4];"
                 : "=r"(r[0]), "=r"(r[1]), "=r"(r[2]), "=r"(r[3]) : "r"(addr));
}
__device__ __forceinline__ void mma16816(float* d, const uint32_t* a, uint32_t b0, uint32_t b1) {
    asm volatile("mma.sync.aligned.m16n8k16.row.col.f32.f16.f16.f32 "
                 "{%0,%1,%2,%3}, {%4,%5,%6,%7}, {%8,%9}, {%0,%1,%2,%3};"
                 : "+f"(d[0]), "+f"(d[1]), "+f"(d[2]), "+f"(d[3])
                 : "r"(a[0]), "r"(a[1]), "r"(a[2]), "r"(a[3]), "r"(b0), "r"(b1));
}
__device__ __forceinline__ float gelu_exact(float x) {
    return 0.5f * x * (1.0f + erff(x * 0.70710678118654752f));
}
__device__ __forceinline__ uint32_t swz(int r, int c2) {
    return (uint32_t)(r * 128 + ((c2 * 16) ^ ((r & 7) * 16)));
}
__device__ __forceinline__ uint32_t pack_h2(__half x, __half y) {
    __half2 v; v.x = x; v.y = y;
    return *(uint32_t*)&v;
}

// ---------------- kernel 1: fused conv (B first, then A) ----------------
__global__ void conv_kernel(const int* __restrict__ cand,
                            const float* __restrict__ encode,
                            const float* __restrict__ W1,
                            const float* __restrict__ b2,
                            float* __restrict__ out) {
    if (blockIdx.x < NBLK_B) {
        __shared__ float tile[32][68];
        const int bb = blockIdx.x;
        const int n0 = (bb & 63) * 64;
        const int k0 = (bb >> 6) * 32;
        {
            const int r  = threadIdx.x >> 4;
            const int c4 = (threadIdx.x & 15) * 4;
            #pragma unroll
            for (int rr = r; rr < 32; rr += 16) {
                float4 v = *(const float4*)&W1[(size_t)(k0 + rr) * DFF_ + n0 + c4];
                *(float4*)&tile[rr][c4] = v;
            }
        }
        __syncthreads();
        {
            const int n  = threadIdx.x & 63;
            const int kq = (threadIdx.x >> 6) * 8;
            uint32_t hi[4];
            #pragma unroll
            for (int i = 0; i < 4; i++) {
                hi[i] = pack_h2(__float2half_rn(tile[kq + 2 * i][n]),
                                __float2half_rn(tile[kq + 2 * i + 1][n]));
            }
            *(uint4*)(g_B2t + (size_t)(n0 + n) * K1 + k0 + kq) = *(uint4*)hi;
        }
    } else {
        const int b0 = (blockIdx.x - NBLK_B) * 4;
        __shared__ int srow[4];
        const int w = threadIdx.x >> 5, lane = threadIdx.x & 31;
        if (w < 4) {
            int c = cand[(b0 + w) * NCAND + lane];
            unsigned m = __ballot_sync(0xffffffffu, c >= NACT);
            if (lane == 0) {
                srow[w] = (S_ - NCAND) + (__ffs(m) - 1);
                out[b0 + w] = b2[0];
            }
        }
        __syncthreads();
        const int i = threadIdx.x;
        #pragma unroll
        for (int r = 0; r < 4; r++) {
            const int b = b0 + r;
            float4 a = ((const float4*)(encode + ((size_t)b * S_ + srow[r]) * D_))[i];
            uint2 hv;
            hv.x = pack_h2(__float2half_rn(a.x), __float2half_rn(a.y));
            hv.y = pack_h2(__float2half_rn(a.z), __float2half_rn(a.w));
            *(uint2*)(g_A2 + (size_t)b * K1 + 4 * i) = hv;
        }
    }
    cudaTriggerProgrammaticLaunchCompletion();
}

// ---------------- kernel 2: fp16 HMMA GEMM, 128x64 CTA tile, 3 CTAs/SM ----------------
__global__ __launch_bounds__(GT, 3)
void gemm_kernel(const float* __restrict__ b1,
                 const float* __restrict__ W2,
                 float* __restrict__ out) {
    extern __shared__ char smem[];
    const uint32_t sb = smem_u32(smem);
    const int tid  = threadIdx.x;
    const int wid  = tid >> 5;
    const int lane = tid & 31;
    const int wm = wid >> 1;     // 0..3 (32 rows each)
    const int wn = wid & 1;      // 0..1 (32 cols each)
    const int bn = blockIdx.x;   // 0..63
    const int bm = blockIdx.y;   // 0..15

    // ---- cp.async mapping: A 4 chunks + B 2 chunks per thread per stage
    const int lr  = tid >> 3;    // 0..31
    const int lc2 = tid & 7;
    const char* aPtr;
    const char* bPtr;
    {
        aPtr = (const char*)(g_A2  + (size_t)(bm * BM + lr) * K1 + lc2 * 8);
        bPtr = (const char*)(g_B2t + (size_t)(bn * BN + lr) * K1 + lc2 * 8);
    }
    const size_t R32 = (size_t)32 * K1 * 2;      // 32 rows of gmem
    const uint32_t aSw0 = swz(lr, lc2);          // +i*32 rows => +i*4096 in smem
    const uint32_t bSw0 = aSw0 + 16384;

    // ---- ldmatrix address constants
    const int l15 = lane & 15;
    const uint32_t xb  = (uint32_t)(l15 & 7) * 16;
    const uint32_t hlx = ((uint32_t)(lane >> 4) * 16) ^ (xb & 16);
    const uint32_t xh  = xb & 0x60;
    const uint32_t aBase = sb + (uint32_t)(wm * 32 + l15) * 128 + hlx;
    const uint32_t bBase = sb + (uint32_t)(wn * 32 + l15) * 128 + hlx + 16384;
    const uint32_t xh0 = 0 ^ xh, xh1 = 32 ^ xh, xh2 = 64 ^ xh, xh3 = 96 ^ xh;

    float acc[2][4][4];
    #pragma unroll
    for (int i = 0; i < 2; i++)
        #pragma unroll
        for (int j = 0; j < 4; j++)
            #pragma unroll
            for (int r = 0; r < 4; r++) acc[i][j][r] = 0.f;

    cudaGridDependencySynchronize();

    #define LOAD_STAGE(buf, c)                                                       \
        do {                                                                         \
            _Pragma("unroll")                                                        \
            for (int i = 0; i < 4; i++)                                              \
                cp_async16(sb + (buf) * STAGE_BYTES + aSw0 + i * 4096,               \
                           aPtr + i * R32 + (c) * 128);                              \
            _Pragma("unroll")                                                        \
            for (int i = 0; i < 2; i++)                                              \
                cp_async16(sb + (buf) * STAGE_BYTES + bSw0 + i * 4096,               \
                           bPtr + i * R32 + (c) * 128);                              \
            CP_COMMIT();                                                             \
        } while (0)

    LOAD_STAGE(0, 0);
    LOAD_STAGE(1, 1);

    #pragma unroll
    for (int c = 0; c < NCH; c++) {
        cp_wait<1>();
        __syncthreads();
        if (c + 2 < NCH) LOAD_STAGE((c + 2) % STAGES, c + 2);

        const uint32_t stg = (uint32_t)((c % STAGES) * STAGE_BYTES);
        const uint32_t ksofs[4] = {stg + xh0, stg + xh1, stg + xh2, stg + xh3};

        #pragma unroll
        for (int ks = 0; ks < 4; ks++) {
            uint32_t afr[2][4], bfr[2][4];
            #pragma unroll
            for (int mt = 0; mt < 2; mt++) ldsm_x4(afr[mt], aBase + ksofs[ks] + mt * 2048);
            #pragma unroll
            for (int u = 0; u < 2; u++)    ldsm_x4(bfr[u],  bBase + ksofs[ks] + u * 2048);
            #pragma unroll
            for (int mt = 0; mt < 2; mt++)
                #pragma unroll
                for (int nt = 0; nt < 4; nt++)
                    mma16816(acc[mt][nt], afr[mt],
                             bfr[nt >> 1][nt & 1], bfr[nt >> 1][(nt & 1) + 2]);
        }
    }

    // ---- Epilogue: bias + exact gelu + dot W2, reduce, atomicAdd ----
    const int qn = lane & 3;
    const int qr = lane >> 2;
    float bia[4][2], w2v[4][2];
    #pragma unroll
    for (int nt = 0; nt < 4; nt++) {
        int n = bn * BN + wn * 32 + nt * 8 + qn * 2;
        bia[nt][0] = __ldg(&b1[n]);     bia[nt][1] = __ldg(&b1[n + 1]);
        w2v[nt][0] = __ldg(&W2[n]);     w2v[nt][1] = __ldg(&W2[n + 1]);
    }
    #pragma unroll
    for (int mt = 0; mt < 2; mt++) {
        float p0 = 0.f, p1 = 0.f;
        #pragma unroll
        for (int nt = 0; nt < 4; nt++) {
            const float* d = acc[mt][nt];
            p0 = fmaf(gelu_exact(d[0] + bia[nt][0]), w2v[nt][0], p0);
            p0 = fmaf(gelu_exact(d[1] + bia[nt][1]), w2v[nt][1], p0);
            p1 = fmaf(gelu_exact(d[2] + bia[nt][0]), w2v[nt][0], p1);
            p1 = fmaf(gelu_exact(d[3] + bia[nt][1]), w2v[nt][1], p1);
        }
        p0 += __shfl_xor_sync(0xffffffffu, p0, 1);
        p0 += __shfl_xor_sync(0xffffffffu, p0, 2);
        p1 += __shfl_xor_sync(0xffffffffu, p1, 1);
        p1 += __shfl_xor_sync(0xffffffffu, p1, 2);
        if (qn == 0) {
            int m = bm * BM + wm * 32 + mt * 16 + qr;
            atomicAdd(&out[m], p0);
            atomicAdd(&out[m + 8], p1);
        }
    }
}

// ---------------- launcher ----------------
extern "C" void kernel_launch(void* const* d_in, const int* in_sizes, int n_in,
                              void* d_out, int out_size) {
    const int*   cand   = (const int*)d_in[0];
    const float* encode = (const float*)d_in[1];
    const float* W1     = (const float*)d_in[2];
    const float* b1     = (const float*)d_in[3];
    const float* W2     = (const float*)d_in[4];
    const float* b2     = (const float*)d_in[5];
    float* out = (float*)d_out;

    static int smem_set = 0;
    if (!smem_set) {
        cudaFuncSetAttribute(gemm_kernel, cudaFuncAttributeMaxDynamicSharedMemorySize, SM_TOTAL);
        smem_set = 1;
    }

    conv_kernel<<<NBLK_B + NBLK_A, 256>>>(cand, encode, W1, b2, out);

    cudaLaunchConfig_t cfg = {};
    cfg.gridDim  = dim3(DFF_ / BN, B_ / BM, 1);   // (64, 16)
    cfg.blockDim = dim3(GT, 1, 1);
    cfg.dynamicSmemBytes = SM_TOTAL;
    cfg.stream = 0;
    cudaLaunchAttribute attrs[1];
    attrs[0].id = cudaLaunchAttributeProgrammaticStreamSerialization;
    attrs[0].val.programmaticStreamSerializationAllowed = 1;
    cfg.attrs = attrs;
    cfg.numAttrs = 1;
    cudaLaunchKernelEx(&cfg, gemm_kernel, b1, W2, out);
}